// round 1
// baseline (speedup 1.0000x reference)
#include <cuda_runtime.h>
#include <cuda_bf16.h>
#include <cstdint>

// Problem constants
#define N_HOST 20000
#define N_FLOW 200000
#define NE     600000
#define D_IN   64
#define D_H    128
#define D_OUT  32

// ---------------- scratch (__device__ globals; no allocation allowed) ----------------
__device__ float g_tx0  [(size_t)N_HOST * D_H];   // x_host @ W0_hf_l
__device__ float g_aggF [(size_t)N_FLOW * D_H];   // scatter of g_tx0 over hf edges
__device__ float g_cntF [N_FLOW];
__device__ float g_aggH [(size_t)N_HOST * D_IN];  // scatter of x_flow over fh edges
__device__ float g_cntH [N_HOST];
__device__ float g_hhost[(size_t)N_HOST * D_H];
__device__ float g_th1  [(size_t)N_HOST * D_H];   // h_host @ W1_hf_l
__device__ float g_hflow[(size_t)N_FLOW * D_H];
__device__ float g_r1   [(size_t)N_FLOW * D_H];   // h_flow @ W1_hf_r
__device__ float g_agg2 [(size_t)N_FLOW * D_H];   // scatter of g_th1 over hf edges

// ---------------- zero scratch ----------------
__global__ void k_zero() {
    size_t i = (size_t)blockIdx.x * blockDim.x + threadIdx.x;
    size_t stride = (size_t)gridDim.x * blockDim.x;
    const float4 z = make_float4(0.f, 0.f, 0.f, 0.f);
    for (size_t k = i; k < ((size_t)N_FLOW * D_H) / 4; k += stride) ((float4*)g_aggF)[k] = z;
    for (size_t k = i; k < ((size_t)N_FLOW * D_H) / 4; k += stride) ((float4*)g_agg2)[k] = z;
    for (size_t k = i; k < ((size_t)N_HOST * D_IN) / 4; k += stride) ((float4*)g_aggH)[k] = z;
    for (size_t k = i; k < (size_t)N_FLOW / 4; k += stride) ((float4*)g_cntF)[k] = z;
    for (size_t k = i; k < (size_t)N_HOST / 4; k += stride) ((float4*)g_cntH)[k] = z;
}

// ---------------- edge scatter: agg[dst] += feat[src]; cnt[dst] += 1 ----------------
// D = 64 or 128. One float4 lane-group per edge (D/4 lanes/edge).
__global__ __launch_bounds__(256) void k_scatter(
    const float* __restrict__ feat, const int* __restrict__ src,
    const int* __restrict__ dst, float* __restrict__ agg,
    float* __restrict__ cnt, int E, int D)
{
    int lpe  = D >> 2;                       // lanes per edge (16 or 32)
    int eloc = threadIdx.x / lpe;
    int lane = threadIdx.x - eloc * lpe;
    int epb  = blockDim.x / lpe;
    int e = blockIdx.x * epb + eloc;
    if (e >= E) return;
    int s = __ldg(src + e);
    int d = __ldg(dst + e);
    float4 v = *(const float4*)(feat + (size_t)s * D + lane * 4);
    float* p = agg + (size_t)d * D + lane * 4;
    asm volatile("red.global.add.v4.f32 [%0], {%1,%2,%3,%4};"
                 :: "l"(p), "f"(v.x), "f"(v.y), "f"(v.z), "f"(v.w) : "memory");
    if (cnt != nullptr && lane == 0) atomicAdd(cnt + d, 1.0f);
}

// ---------------- generic fused SAGE GEMM ----------------
// C[M,128] = act( (A1/cnt1) @ W1 + A2 @ W2 + pre/cntp + bias )
// K1, K2 in {0, 64, 128}; any pointer may be null to disable that term.
#define BM 64
#define BK 32
#define BN 128

__global__ __launch_bounds__(256) void sage_gemm(
    const float* __restrict__ A1, const float* __restrict__ W1, int K1,
    const float* __restrict__ cnt1,
    const float* __restrict__ A2, const float* __restrict__ W2, int K2,
    const float* __restrict__ pre, const float* __restrict__ cntp,
    const float* __restrict__ bias, int act,
    float* __restrict__ C, int M)
{
    __shared__ float As[BM][BK + 4];   // 64 x 36 (pad: conflict-free column reads)
    __shared__ float Ws[BK][BN];       // 32 x 128

    const int tid = threadIdx.x;
    const int block_row = blockIdx.x * BM;
    const int tr = tid >> 4;           // 0..15 -> rows tr*4 .. tr*4+3
    const int tc = tid & 15;           // 0..15 -> cols tc*8 .. tc*8+7

    float acc[4][8];
#pragma unroll
    for (int i = 0; i < 4; i++)
#pragma unroll
        for (int j = 0; j < 8; j++) acc[i][j] = 0.f;

    for (int term = 0; term < 2; term++) {
        const float* A = term ? A2 : A1;
        const float* W = term ? W2 : W1;
        const float* cs = term ? nullptr : cnt1;
        int K = term ? K2 : K1;
        if (A == nullptr || K == 0) continue;

        for (int kb = 0; kb < K; kb += BK) {
            __syncthreads();
            // load A tile: 64 rows x 32 cols, 2 float4 per thread
#pragma unroll
            for (int it = 0; it < 2; it++) {
                int r  = (tid >> 3) + it * 32;
                int c4 = (tid & 7) * 4;
                int gr = block_row + r;
                float4 v = make_float4(0.f, 0.f, 0.f, 0.f);
                if (gr < M) {
                    v = *(const float4*)(A + (size_t)gr * K + kb + c4);
                    if (cs != nullptr) {
                        float inv = 1.f / fmaxf(cs[gr], 1.f);
                        v.x *= inv; v.y *= inv; v.z *= inv; v.w *= inv;
                    }
                }
                *(float4*)(&As[r][c4]) = v;
            }
            // load W tile: 32 x 128, 4 float4 per thread
#pragma unroll
            for (int it = 0; it < 4; it++) {
                int idx = tid + it * 256;        // float4 index 0..1023
                int r   = idx >> 5;              // 0..31
                int c4  = (idx & 31) * 4;
                *(float4*)(&Ws[r][c4]) = *(const float4*)(W + (size_t)(kb + r) * BN + c4);
            }
            __syncthreads();

#pragma unroll
            for (int kk = 0; kk < BK; kk++) {
                float a[4];
#pragma unroll
                for (int i = 0; i < 4; i++) a[i] = As[tr * 4 + i][kk];
                float4 b0 = *(float4*)(&Ws[kk][tc * 8]);
                float4 b1 = *(float4*)(&Ws[kk][tc * 8 + 4]);
                float b[8] = {b0.x, b0.y, b0.z, b0.w, b1.x, b1.y, b1.z, b1.w};
#pragma unroll
                for (int i = 0; i < 4; i++)
#pragma unroll
                    for (int j = 0; j < 8; j++) acc[i][j] += a[i] * b[j];
            }
        }
    }

    // epilogue
#pragma unroll
    for (int i = 0; i < 4; i++) {
        int gr = block_row + tr * 4 + i;
        if (gr >= M) continue;
        float vals[8];
#pragma unroll
        for (int j = 0; j < 8; j++) vals[j] = acc[i][j];
        if (pre != nullptr) {
            float ip = (cntp != nullptr) ? (1.f / fmaxf(cntp[gr], 1.f)) : 1.f;
            const float4 p0 = *(const float4*)(pre + (size_t)gr * BN + tc * 8);
            const float4 p1 = *(const float4*)(pre + (size_t)gr * BN + tc * 8 + 4);
            vals[0] += p0.x * ip; vals[1] += p0.y * ip; vals[2] += p0.z * ip; vals[3] += p0.w * ip;
            vals[4] += p1.x * ip; vals[5] += p1.y * ip; vals[6] += p1.z * ip; vals[7] += p1.w * ip;
        }
        if (bias != nullptr) {
#pragma unroll
            for (int j = 0; j < 8; j++) vals[j] += __ldg(bias + tc * 8 + j);
        }
        if (act) {
#pragma unroll
            for (int j = 0; j < 8; j++) vals[j] = vals[j] > 0.f ? vals[j] : 0.01f * vals[j];
        }
        float4 o0 = make_float4(vals[0], vals[1], vals[2], vals[3]);
        float4 o1 = make_float4(vals[4], vals[5], vals[6], vals[7]);
        *(float4*)(C + (size_t)gr * BN + tc * 8)     = o0;
        *(float4*)(C + (size_t)gr * BN + tc * 8 + 4) = o1;
    }
}

// ---------------- final: out = lrelu(agg2/cnt + r1 + b1) @ W_out + b_out ----------------
#define FBM 32
__global__ __launch_bounds__(256) void k_final(
    const float* __restrict__ r1, const float* __restrict__ agg2,
    const float* __restrict__ cnt, const float* __restrict__ b1,
    const float* __restrict__ Wout, const float* __restrict__ bout,
    float* __restrict__ out, int M)
{
    __shared__ float gs[FBM][136];    // padded (136*4 % 16 == 0, conflict-free)
    __shared__ float ws[D_H][D_OUT];  // 128 x 32

    const int tid = threadIdx.x;
    const int row0 = blockIdx.x * FBM;

    // load W_out: 4096 floats = 1024 float4, 4 per thread
#pragma unroll
    for (int it = 0; it < 4; it++) {
        int idx = tid + it * 256;       // float4 index
        int r = idx >> 3, c4 = (idx & 7) * 4;
        *(float4*)(&ws[r][c4]) = *(const float4*)(Wout + (size_t)idx * 4);
    }

    // compute g tile (32 rows x 128): 1024 float4, 4 per thread
#pragma unroll
    for (int it = 0; it < 4; it++) {
        int idx = tid + it * 256;
        int r = idx >> 5, c4 = (idx & 31) * 4;
        int gr = row0 + r;
        float inv = 1.f / fmaxf(cnt[gr], 1.f);
        float4 a = *(const float4*)(agg2 + (size_t)gr * D_H + c4);
        float4 b = *(const float4*)(r1   + (size_t)gr * D_H + c4);
        float4 bb = *(const float4*)(b1 + c4);
        float4 g;
        g.x = a.x * inv + b.x + bb.x;
        g.y = a.y * inv + b.y + bb.y;
        g.z = a.z * inv + b.z + bb.z;
        g.w = a.w * inv + b.w + bb.w;
        g.x = g.x > 0.f ? g.x : 0.01f * g.x;
        g.y = g.y > 0.f ? g.y : 0.01f * g.y;
        g.z = g.z > 0.f ? g.z : 0.01f * g.z;
        g.w = g.w > 0.f ? g.w : 0.01f * g.w;
        *(float4*)(&gs[r][c4]) = g;
    }
    __syncthreads();

    // out tile 32x32: each thread 1 row x 4 cols
    const int r = tid >> 3;
    const int c = (tid & 7) * 4;
    float acc0 = __ldg(bout + c), acc1 = __ldg(bout + c + 1);
    float acc2 = __ldg(bout + c + 2), acc3 = __ldg(bout + c + 3);
#pragma unroll 8
    for (int k = 0; k < D_H; k++) {
        float gv = gs[r][k];
        float4 w = *(float4*)(&ws[k][c]);
        acc0 += gv * w.x; acc1 += gv * w.y; acc2 += gv * w.z; acc3 += gv * w.w;
    }
    int gr = row0 + r;
    if (gr < M) {
        float4 o = make_float4(acc0, acc1, acc2, acc3);
        *(float4*)(out + (size_t)gr * D_OUT + c) = o;
    }
}

// ---------------- host launcher ----------------
extern "C" void kernel_launch(void* const* d_in, const int* in_sizes, int n_in,
                              void* d_out, int out_size)
{
    const float* x_host  = (const float*)d_in[0];
    const float* x_flow  = (const float*)d_in[1];
    const int*   src_hf  = (const int*)d_in[2];
    const int*   dst_hf  = (const int*)d_in[3];
    const int*   src_fh  = (const int*)d_in[4];
    const int*   dst_fh  = (const int*)d_in[5];
    const float* W0_hf_l = (const float*)d_in[6];
    const float* W0_hf_r = (const float*)d_in[7];
    const float* b0_hf   = (const float*)d_in[8];
    const float* W0_fh_l = (const float*)d_in[9];
    const float* W0_fh_r = (const float*)d_in[10];
    const float* b0_fh   = (const float*)d_in[11];
    const float* W1_hf_l = (const float*)d_in[12];
    const float* W1_hf_r = (const float*)d_in[13];
    const float* b1_hf   = (const float*)d_in[14];
    // d_in[15..17] = W1_fh_l, W1_fh_r, b1_fh: unused (g_host is discarded)
    const float* W_out   = (const float*)d_in[18];
    const float* b_out   = (const float*)d_in[19];
    float* out = (float*)d_out;

    float *tx0, *aggF, *cntF, *aggH, *cntH, *hhost, *th1, *hflow, *r1, *agg2;
    cudaGetSymbolAddress((void**)&tx0,   g_tx0);
    cudaGetSymbolAddress((void**)&aggF,  g_aggF);
    cudaGetSymbolAddress((void**)&cntF,  g_cntF);
    cudaGetSymbolAddress((void**)&aggH,  g_aggH);
    cudaGetSymbolAddress((void**)&cntH,  g_cntH);
    cudaGetSymbolAddress((void**)&hhost, g_hhost);
    cudaGetSymbolAddress((void**)&th1,   g_th1);
    cudaGetSymbolAddress((void**)&hflow, g_hflow);
    cudaGetSymbolAddress((void**)&r1,    g_r1);
    cudaGetSymbolAddress((void**)&agg2,  g_agg2);

    // 1. zero accumulators
    k_zero<<<2048, 256>>>();

    // 2. tx0 = x_host @ W0_hf_l   (transform-then-scatter for hf layer 0)
    sage_gemm<<<(N_HOST + BM - 1) / BM, 256>>>(
        x_host, W0_hf_l, D_IN, nullptr,
        nullptr, nullptr, 0, nullptr, nullptr, nullptr, 0, tx0, N_HOST);

    // 3. aggF[dst_hf] += tx0[src_hf]; cntF++   (128-dim)
    k_scatter<<<(NE + 7) / 8, 256>>>(tx0, src_hf, dst_hf, aggF, cntF, NE, D_H);

    // 4. aggH[dst_fh] += x_flow[src_fh]; cntH++   (64-dim, scatter-then-transform)
    k_scatter<<<(NE + 15) / 16, 256>>>(x_flow, src_fh, dst_fh, aggH, cntH, NE, D_IN);

    // 5. h_host = lrelu((aggH/cntH) @ W0_fh_l + x_host @ W0_fh_r + b0_fh)
    sage_gemm<<<(N_HOST + BM - 1) / BM, 256>>>(
        aggH, W0_fh_l, D_IN, cntH,
        x_host, W0_fh_r, D_IN, nullptr, nullptr, b0_fh, 1, hhost, N_HOST);

    // 6. th1 = h_host @ W1_hf_l
    sage_gemm<<<(N_HOST + BM - 1) / BM, 256>>>(
        hhost, W1_hf_l, D_H, nullptr,
        nullptr, nullptr, 0, nullptr, nullptr, nullptr, 0, th1, N_HOST);

    // 7. h_flow = lrelu(aggF/cntF + x_flow @ W0_hf_r + b0_hf)
    sage_gemm<<<N_FLOW / BM, 256>>>(
        x_flow, W0_hf_r, D_IN, nullptr,
        nullptr, nullptr, 0, aggF, cntF, b0_hf, 1, hflow, N_FLOW);

    // 8. r1 = h_flow @ W1_hf_r
    sage_gemm<<<N_FLOW / BM, 256>>>(
        hflow, W1_hf_r, D_H, nullptr,
        nullptr, nullptr, 0, nullptr, nullptr, nullptr, 0, r1, N_FLOW);

    // 9. agg2[dst_hf] += th1[src_hf]   (counts identical to cntF)
    k_scatter<<<(NE + 7) / 8, 256>>>(th1, src_hf, dst_hf, agg2, nullptr, NE, D_H);

    // 10. out = lrelu(agg2/cntF + r1 + b1_hf) @ W_out + b_out
    k_final<<<N_FLOW / FBM, 256>>>(r1, agg2, cntF, b1_hf, W_out, b_out, out, N_FLOW);
}

// round 2
// speedup vs baseline: 1.1773x; 1.1773x over previous
#include <cuda_runtime.h>
#include <cuda_bf16.h>
#include <cstdint>

// Problem constants
#define N_HOST 20000
#define N_FLOW 200000
#define NE     600000
#define D_IN   64
#define D_H    128
#define D_OUT  32

typedef unsigned long long ull;

// ---------------- scratch (__device__ globals; no allocation allowed) ----------------
__device__ float g_tx0  [(size_t)N_HOST * D_H];   // x_host @ W0_hf_l
__device__ float g_xr   [(size_t)N_HOST * D_H];   // x_host @ W0_fh_r
__device__ float g_aggF [(size_t)N_FLOW * D_H];   // scatter of g_tx0 over hf edges
__device__ float g_cntF [N_FLOW];
__device__ float g_aggH [(size_t)N_HOST * D_IN];  // scatter of x_flow over fh edges
__device__ float g_cntH [N_HOST];
__device__ float g_th1  [(size_t)N_HOST * D_H];   // h_host @ W1_hf_l
__device__ float g_agg2 [(size_t)N_FLOW * D_H];   // scatter of g_th1 over hf edges

// ---------------- f32x2 packed-FMA helpers ----------------
__device__ __forceinline__ ull dup2(float x) {
    ull r; asm("mov.b64 %0, {%1, %1};" : "=l"(r) : "f"(x)); return r;
}
__device__ __forceinline__ void ffma2(ull& acc, ull a, ull b) {
    asm("fma.rn.f32x2 %0, %1, %2, %0;" : "+l"(acc) : "l"(a), "l"(b));
}
__device__ __forceinline__ float lrelu(float v) { return v > 0.f ? v : 0.01f * v; }

// ---------------- core register-tile MMA ----------------
// acc[8][4] f32x2 pairs covering rows tr8..tr8+7, cols tc8..tc8+7.
// As: row-major [*, AP], Ws: row-major [K][128].
template <int K, int AP>
__device__ __forceinline__ void mma_tile(const float* __restrict__ As,
                                         const float* __restrict__ Ws,
                                         int tr8, int tc8, ull acc[8][4])
{
#pragma unroll 4
    for (int kk = 0; kk < K; kk++) {
        const ulonglong2* wp = reinterpret_cast<const ulonglong2*>(Ws + kk * 128 + tc8);
        ulonglong2 w01 = wp[0];
        ulonglong2 w23 = wp[1];
        ull ad[8];
#pragma unroll
        for (int i = 0; i < 8; i++) ad[i] = dup2(As[(tr8 + i) * AP + kk]);
#pragma unroll
        for (int i = 0; i < 8; i++) {
            ffma2(acc[i][0], ad[i], w01.x);
            ffma2(acc[i][1], ad[i], w01.y);
            ffma2(acc[i][2], ad[i], w23.x);
            ffma2(acc[i][3], ad[i], w23.y);
        }
    }
}

__device__ __forceinline__ void zero_acc(ull acc[8][4]) {
#pragma unroll
    for (int i = 0; i < 8; i++)
#pragma unroll
        for (int p = 0; p < 4; p++) acc[i][p] = 0ull;
}

// ---------------- zero scratch ----------------
__global__ void k_zero() {
    size_t i = (size_t)blockIdx.x * blockDim.x + threadIdx.x;
    size_t stride = (size_t)gridDim.x * blockDim.x;
    const float4 z = make_float4(0.f, 0.f, 0.f, 0.f);
    for (size_t k = i; k < ((size_t)N_FLOW * D_H) / 4; k += stride) ((float4*)g_aggF)[k] = z;
    for (size_t k = i; k < ((size_t)N_FLOW * D_H) / 4; k += stride) ((float4*)g_agg2)[k] = z;
    for (size_t k = i; k < ((size_t)N_HOST * D_IN) / 4; k += stride) ((float4*)g_aggH)[k] = z;
    for (size_t k = i; k < (size_t)N_FLOW / 4; k += stride) ((float4*)g_cntF)[k] = z;
    for (size_t k = i; k < (size_t)N_HOST / 4; k += stride) ((float4*)g_cntH)[k] = z;
}

// ---------------- edge scatter: agg[dst] += feat[src]; cnt[dst] += 1 ----------------
__global__ __launch_bounds__(256) void k_scatter(
    const float* __restrict__ feat, const int* __restrict__ src,
    const int* __restrict__ dst, float* __restrict__ agg,
    float* __restrict__ cnt, int E, int D)
{
    int lpe  = D >> 2;
    int eloc = threadIdx.x / lpe;
    int lane = threadIdx.x - eloc * lpe;
    int epb  = blockDim.x / lpe;
    int e = blockIdx.x * epb + eloc;
    if (e >= E) return;
    int s = __ldg(src + e);
    int d = __ldg(dst + e);
    float4 v = *(const float4*)(feat + (size_t)s * D + lane * 4);
    float* p = agg + (size_t)d * D + lane * 4;
    asm volatile("red.global.add.v4.f32 [%0], {%1,%2,%3,%4};"
                 :: "l"(p), "f"(v.x), "f"(v.y), "f"(v.z), "f"(v.w) : "memory");
    if (cnt != nullptr && lane == 0) atomicAdd(cnt + d, 1.0f);
}

// ---------------- dual small GEMM: tx0 = x_host@Wa ; xr = x_host@Wb  (K=64) ----------------
struct DualSmem {
    float Wa[64 * 128];
    float Wb[64 * 128];
    float Asf[128 * 68];
};

extern __shared__ char smem_raw[];

__global__ __launch_bounds__(256, 1) void k_dual(
    const float* __restrict__ xh,
    const float* __restrict__ Wla, const float* __restrict__ Wlb,
    float* __restrict__ Ca, float* __restrict__ Cb)
{
    DualSmem* S = reinterpret_cast<DualSmem*>(smem_raw);
    const int tid = threadIdx.x;
    for (int f = tid; f < 64 * 128 / 4; f += 256) {
        ((float4*)S->Wa)[f] = ((const float4*)Wla)[f];
        ((float4*)S->Wb)[f] = ((const float4*)Wlb)[f];
    }
    const int tr8 = (tid >> 4) * 8;
    const int tc8 = (tid & 15) * 8;

    const int NT = (N_HOST + 127) / 128;
    for (int tile = blockIdx.x; tile < NT; tile += gridDim.x) {
        const int row0 = tile * 128;
        __syncthreads();
        for (int f = tid; f < 2048; f += 256) {
            int r = f >> 4, cc = (f & 15) * 4;
            int gr = row0 + r;
            if (gr < N_HOST)
                *(float4*)(S->Asf + r * 68 + cc) = *(const float4*)(xh + (size_t)gr * 64 + cc);
        }
        __syncthreads();

        ull acc[8][4];
        zero_acc(acc);
        mma_tile<64, 68>(S->Asf, S->Wa, tr8, tc8, acc);
#pragma unroll
        for (int i = 0; i < 8; i++) {
            int gr = row0 + tr8 + i;
            if (gr >= N_HOST) continue;
            float4 o0, o1;
            float2 v0 = *reinterpret_cast<float2*>(&acc[i][0]);
            float2 v1 = *reinterpret_cast<float2*>(&acc[i][1]);
            float2 v2 = *reinterpret_cast<float2*>(&acc[i][2]);
            float2 v3 = *reinterpret_cast<float2*>(&acc[i][3]);
            o0 = make_float4(v0.x, v0.y, v1.x, v1.y);
            o1 = make_float4(v2.x, v2.y, v3.x, v3.y);
            *(float4*)(Ca + (size_t)gr * 128 + tc8)     = o0;
            *(float4*)(Ca + (size_t)gr * 128 + tc8 + 4) = o1;
        }
        zero_acc(acc);
        mma_tile<64, 68>(S->Asf, S->Wb, tr8, tc8, acc);
#pragma unroll
        for (int i = 0; i < 8; i++) {
            int gr = row0 + tr8 + i;
            if (gr >= N_HOST) continue;
            float2 v0 = *reinterpret_cast<float2*>(&acc[i][0]);
            float2 v1 = *reinterpret_cast<float2*>(&acc[i][1]);
            float2 v2 = *reinterpret_cast<float2*>(&acc[i][2]);
            float2 v3 = *reinterpret_cast<float2*>(&acc[i][3]);
            *(float4*)(Cb + (size_t)gr * 128 + tc8)     = make_float4(v0.x, v0.y, v1.x, v1.y);
            *(float4*)(Cb + (size_t)gr * 128 + tc8 + 4) = make_float4(v2.x, v2.y, v3.x, v3.y);
        }
    }
}

// ---------------- fused host chain: th1 = (lrelu(aggH/cnt @ W0l + xr + b0)) @ W1l ----------------
struct HostSmem {
    float Ws0[64 * 128];
    float Ws1[128 * 128];
    float Asf[128 * 68];
    float H[128 * 132];
};

__global__ __launch_bounds__(256, 1) void k_host(
    const float* __restrict__ aggH, const float* __restrict__ cntH,
    const float* __restrict__ xr,
    const float* __restrict__ W0l, const float* __restrict__ b0,
    const float* __restrict__ W1l,
    float* __restrict__ th1)
{
    HostSmem* S = reinterpret_cast<HostSmem*>(smem_raw);
    const int tid = threadIdx.x;
    for (int f = tid; f < 64 * 128 / 4; f += 256) ((float4*)S->Ws0)[f] = ((const float4*)W0l)[f];
    for (int f = tid; f < 128 * 128 / 4; f += 256) ((float4*)S->Ws1)[f] = ((const float4*)W1l)[f];

    const int tr8 = (tid >> 4) * 8;
    const int tc8 = (tid & 15) * 8;
    float b0r[8];
#pragma unroll
    for (int j = 0; j < 8; j++) b0r[j] = b0[tc8 + j];

    const int NT = (N_HOST + 127) / 128;
    for (int tile = blockIdx.x; tile < NT; tile += gridDim.x) {
        const int row0 = tile * 128;
        __syncthreads();
        // load aggH tile pre-scaled by 1/max(cnt,1)
        for (int f = tid; f < 2048; f += 256) {
            int r = f >> 4, cc = (f & 15) * 4;
            int gr = row0 + r;
            if (gr < N_HOST) {
                float inv = 1.f / fmaxf(__ldg(cntH + gr), 1.f);
                float4 v = *(const float4*)(aggH + (size_t)gr * 64 + cc);
                v.x *= inv; v.y *= inv; v.z *= inv; v.w *= inv;
                *(float4*)(S->Asf + r * 68 + cc) = v;
            }
        }
        __syncthreads();

        ull acc[8][4];
        zero_acc(acc);
        mma_tile<64, 68>(S->Asf, S->Ws0, tr8, tc8, acc);

        // epilogue1: H = lrelu(acc + xr + b0)
#pragma unroll
        for (int i = 0; i < 8; i++) {
            int gr = row0 + tr8 + i;
            if (gr >= N_HOST) continue;
            float4 p0 = *(const float4*)(xr + (size_t)gr * 128 + tc8);
            float4 p1 = *(const float4*)(xr + (size_t)gr * 128 + tc8 + 4);
            float pv[8] = {p0.x, p0.y, p0.z, p0.w, p1.x, p1.y, p1.z, p1.w};
#pragma unroll
            for (int p = 0; p < 4; p++) {
                float2 v = *reinterpret_cast<float2*>(&acc[i][p]);
                S->H[(tr8 + i) * 132 + tc8 + 2 * p]     = lrelu(v.x + pv[2 * p] + b0r[2 * p]);
                S->H[(tr8 + i) * 132 + tc8 + 2 * p + 1] = lrelu(v.y + pv[2 * p + 1] + b0r[2 * p + 1]);
            }
        }
        __syncthreads();

        zero_acc(acc);
        mma_tile<128, 132>(S->H, S->Ws1, tr8, tc8, acc);
#pragma unroll
        for (int i = 0; i < 8; i++) {
            int gr = row0 + tr8 + i;
            if (gr >= N_HOST) continue;
            float2 v0 = *reinterpret_cast<float2*>(&acc[i][0]);
            float2 v1 = *reinterpret_cast<float2*>(&acc[i][1]);
            float2 v2 = *reinterpret_cast<float2*>(&acc[i][2]);
            float2 v3 = *reinterpret_cast<float2*>(&acc[i][3]);
            *(float4*)(th1 + (size_t)gr * 128 + tc8)     = make_float4(v0.x, v0.y, v1.x, v1.y);
            *(float4*)(th1 + (size_t)gr * 128 + tc8 + 4) = make_float4(v2.x, v2.y, v3.x, v3.y);
        }
    }
}

// ---------------- fused flow chain (3 phases) ----------------
// hflow = lrelu(x_flow@W0r + aggF/cnt + b0); r1 = hflow@W1r;
// g = lrelu(r1 + agg2/cnt + b1); out = g@Wout + bout
struct FlowSmem {
    float Ws0[64 * 128];    // W0_hf_r
    float Ws1[128 * 128];   // W1_hf_r
    float Wso[128 * 32];    // W_out
    float Asf[128 * 68];    // x_flow tile
    float H[128 * 132];     // hflow, then g
};

__global__ __launch_bounds__(256, 1) void k_flow(
    const float* __restrict__ x_flow,
    const float* __restrict__ aggF, const float* __restrict__ agg2,
    const float* __restrict__ cntF,
    const float* __restrict__ W0r, const float* __restrict__ b0,
    const float* __restrict__ W1r, const float* __restrict__ b1,
    const float* __restrict__ Wout, const float* __restrict__ bout,
    float* __restrict__ out)
{
    FlowSmem* S = reinterpret_cast<FlowSmem*>(smem_raw);
    const int tid = threadIdx.x;
    for (int f = tid; f < 64 * 128 / 4; f += 256) ((float4*)S->Ws0)[f] = ((const float4*)W0r)[f];
    for (int f = tid; f < 128 * 128 / 4; f += 256) ((float4*)S->Ws1)[f] = ((const float4*)W1r)[f];
    for (int f = tid; f < 128 * 32 / 4; f += 256) ((float4*)S->Wso)[f] = ((const float4*)Wout)[f];

    const int tr8 = (tid >> 4) * 8;
    const int tc8 = (tid & 15) * 8;
    float b0r[8], b1r[8];
#pragma unroll
    for (int j = 0; j < 8; j++) { b0r[j] = b0[tc8 + j]; b1r[j] = b1[tc8 + j]; }
    // phase-3 mapping: 4 rows x 4 cols per thread
    const int r4 = (tid >> 3) * 4;   // 0..124
    const int c4 = (tid & 7) * 4;    // 0..28
    float bor[4];
#pragma unroll
    for (int j = 0; j < 4; j++) bor[j] = bout[c4 + j];

    const int NT = (N_FLOW + 127) / 128;
    for (int tile = blockIdx.x; tile < NT; tile += gridDim.x) {
        const int row0 = tile * 128;
        __syncthreads();   // weights ready (iter 0) / prior-iter phase3 readers done
        for (int f = tid; f < 2048; f += 256) {
            int r = f >> 4, cc = (f & 15) * 4;
            int gr = row0 + r;
            if (gr < N_FLOW)
                *(float4*)(S->Asf + r * 68 + cc) = *(const float4*)(x_flow + (size_t)gr * 64 + cc);
        }
        __syncthreads();

        // ---- phase 1: hflow ----
        ull acc[8][4];
        zero_acc(acc);
        mma_tile<64, 68>(S->Asf, S->Ws0, tr8, tc8, acc);
#pragma unroll
        for (int i = 0; i < 8; i++) {
            int gr = row0 + tr8 + i;
            if (gr >= N_FLOW) continue;
            float inv = 1.f / fmaxf(__ldg(cntF + gr), 1.f);
            float4 p0 = *(const float4*)(aggF + (size_t)gr * 128 + tc8);
            float4 p1 = *(const float4*)(aggF + (size_t)gr * 128 + tc8 + 4);
            float pv[8] = {p0.x, p0.y, p0.z, p0.w, p1.x, p1.y, p1.z, p1.w};
#pragma unroll
            for (int p = 0; p < 4; p++) {
                float2 v = *reinterpret_cast<float2*>(&acc[i][p]);
                S->H[(tr8 + i) * 132 + tc8 + 2 * p]     = lrelu(v.x + pv[2 * p] * inv + b0r[2 * p]);
                S->H[(tr8 + i) * 132 + tc8 + 2 * p + 1] = lrelu(v.y + pv[2 * p + 1] * inv + b0r[2 * p + 1]);
            }
        }
        __syncthreads();

        // ---- phase 2: r1 then g ----
        zero_acc(acc);
        mma_tile<128, 132>(S->H, S->Ws1, tr8, tc8, acc);
        __syncthreads();   // all H reads done before overwrite with g
#pragma unroll
        for (int i = 0; i < 8; i++) {
            int gr = row0 + tr8 + i;
            if (gr >= N_FLOW) continue;
            float inv = 1.f / fmaxf(__ldg(cntF + gr), 1.f);
            float4 p0 = *(const float4*)(agg2 + (size_t)gr * 128 + tc8);
            float4 p1 = *(const float4*)(agg2 + (size_t)gr * 128 + tc8 + 4);
            float pv[8] = {p0.x, p0.y, p0.z, p0.w, p1.x, p1.y, p1.z, p1.w};
#pragma unroll
            for (int p = 0; p < 4; p++) {
                float2 v = *reinterpret_cast<float2*>(&acc[i][p]);
                S->H[(tr8 + i) * 132 + tc8 + 2 * p]     = lrelu(v.x + pv[2 * p] * inv + b1r[2 * p]);
                S->H[(tr8 + i) * 132 + tc8 + 2 * p + 1] = lrelu(v.y + pv[2 * p + 1] * inv + b1r[2 * p + 1]);
            }
        }
        __syncthreads();

        // ---- phase 3: out = g @ Wout + bout ----
        ull acc3[4][2];
#pragma unroll
        for (int i = 0; i < 4; i++) { acc3[i][0] = 0ull; acc3[i][1] = 0ull; }
#pragma unroll 4
        for (int kk = 0; kk < 128; kk++) {
            ulonglong2 w = *reinterpret_cast<const ulonglong2*>(S->Wso + kk * 32 + c4);
#pragma unroll
            for (int i = 0; i < 4; i++) {
                ull ad = dup2(S->H[(r4 + i) * 132 + kk]);
                ffma2(acc3[i][0], ad, w.x);
                ffma2(acc3[i][1], ad, w.y);
            }
        }
#pragma unroll
        for (int i = 0; i < 4; i++) {
            int gr = row0 + r4 + i;
            if (gr >= N_FLOW) continue;
            float2 v0 = *reinterpret_cast<float2*>(&acc3[i][0]);
            float2 v1 = *reinterpret_cast<float2*>(&acc3[i][1]);
            *(float4*)(out + (size_t)gr * 32 + c4) =
                make_float4(v0.x + bor[0], v0.y + bor[1], v1.x + bor[2], v1.y + bor[3]);
        }
    }
}

// ---------------- host launcher ----------------
extern "C" void kernel_launch(void* const* d_in, const int* in_sizes, int n_in,
                              void* d_out, int out_size)
{
    const float* x_host  = (const float*)d_in[0];
    const float* x_flow  = (const float*)d_in[1];
    const int*   src_hf  = (const int*)d_in[2];
    const int*   dst_hf  = (const int*)d_in[3];
    const int*   src_fh  = (const int*)d_in[4];
    const int*   dst_fh  = (const int*)d_in[5];
    const float* W0_hf_l = (const float*)d_in[6];
    const float* W0_hf_r = (const float*)d_in[7];
    const float* b0_hf   = (const float*)d_in[8];
    const float* W0_fh_l = (const float*)d_in[9];
    const float* W0_fh_r = (const float*)d_in[10];
    const float* b0_fh   = (const float*)d_in[11];
    const float* W1_hf_l = (const float*)d_in[12];
    const float* W1_hf_r = (const float*)d_in[13];
    const float* b1_hf   = (const float*)d_in[14];
    // d_in[15..17] unused (g_host discarded)
    const float* W_out   = (const float*)d_in[18];
    const float* b_out   = (const float*)d_in[19];
    float* out = (float*)d_out;

    float *tx0, *xr, *aggF, *cntF, *aggH, *cntH, *th1, *agg2;
    cudaGetSymbolAddress((void**)&tx0,  g_tx0);
    cudaGetSymbolAddress((void**)&xr,   g_xr);
    cudaGetSymbolAddress((void**)&aggF, g_aggF);
    cudaGetSymbolAddress((void**)&cntF, g_cntF);
    cudaGetSymbolAddress((void**)&aggH, g_aggH);
    cudaGetSymbolAddress((void**)&cntH, g_cntH);
    cudaGetSymbolAddress((void**)&th1,  g_th1);
    cudaGetSymbolAddress((void**)&agg2, g_agg2);

    cudaFuncSetAttribute(k_dual, cudaFuncAttributeMaxDynamicSharedMemorySize, (int)sizeof(DualSmem));
    cudaFuncSetAttribute(k_host, cudaFuncAttributeMaxDynamicSharedMemorySize, (int)sizeof(HostSmem));
    cudaFuncSetAttribute(k_flow, cudaFuncAttributeMaxDynamicSharedMemorySize, (int)sizeof(FlowSmem));

    // 1. zero accumulators
    k_zero<<<2048, 256>>>();

    // 2. tx0 = x_host @ W0_hf_l ; xr = x_host @ W0_fh_r
    k_dual<<<157, 256, sizeof(DualSmem)>>>(x_host, W0_hf_l, W0_fh_r, tx0, xr);

    // 3. aggH[dst_fh] += x_flow[src_fh]; cntH++   (64-dim)
    k_scatter<<<(NE + 15) / 16, 256>>>(x_flow, src_fh, dst_fh, aggH, cntH, NE, D_IN);

    // 4. aggF[dst_hf] += tx0[src_hf]; cntF++   (128-dim)
    k_scatter<<<(NE + 7) / 8, 256>>>(tx0, src_hf, dst_hf, aggF, cntF, NE, D_H);

    // 5. fused host chain -> th1
    k_host<<<152, 256, sizeof(HostSmem)>>>(aggH, cntH, xr, W0_fh_l, b0_fh, W1_hf_l, th1);

    // 6. agg2[dst_hf] += th1[src_hf]
    k_scatter<<<(NE + 7) / 8, 256>>>(th1, src_hf, dst_hf, agg2, nullptr, NE, D_H);

    // 7. fused flow chain -> out
    k_flow<<<152, 256, sizeof(FlowSmem)>>>(x_flow, aggF, agg2, cntF,
                                           W0_hf_r, b0_hf, W1_hf_r, b1_hf,
                                           W_out, b_out, out);
}

// round 4
// speedup vs baseline: 1.5572x; 1.3227x over previous
#include <cuda_runtime.h>
#include <cuda_bf16.h>
#include <cstdint>

// Problem constants
#define N_HOST 20000
#define N_FLOW 200000
#define NE     600000
#define D_IN   64
#define D_H    128
#define D_OUT  32

typedef unsigned long long ull;

// Does the device pass support tcgen05 (arch-specific 'a' target)?
#if defined(__CUDA_ARCH_FEAT_SM103_ALL) || defined(__CUDA_ARCH_FEAT_SM100_ALL) || defined(__CUDA_ARCH_FEAT_SM101_ALL)
#define HAS_TCGEN05 1
#else
#define HAS_TCGEN05 0
#endif

// ---------------- scratch (__device__ globals) ----------------
__device__ float g_tx0  [(size_t)N_HOST * D_H];
__device__ float g_xr   [(size_t)N_HOST * D_H];
__device__ float g_aggF [(size_t)N_FLOW * D_H];
__device__ float g_cntF [N_FLOW];
__device__ float g_aggH [(size_t)N_HOST * D_IN];
__device__ float g_cntH [N_HOST];
__device__ float g_th1  [(size_t)N_HOST * D_H];
__device__ float g_agg2 [(size_t)N_FLOW * D_H];

extern __shared__ char smem_raw[];

// ---------------- generic helpers ----------------
__device__ __forceinline__ float lrelu(float v) { return v > 0.f ? v : 0.01f * v; }

__device__ __forceinline__ uint32_t smem_u32(const void* p) {
    uint32_t a;
    asm("{ .reg .u64 t; cvta.to.shared.u64 t, %1; cvt.u32.u64 %0, t; }" : "=r"(a) : "l"(p));
    return a;
}

// ---------------- f32x2 packed-FMA helpers ----------------
__device__ __forceinline__ ull dup2(float x) {
    ull r; asm("mov.b64 %0, {%1, %1};" : "=l"(r) : "f"(x)); return r;
}
__device__ __forceinline__ void ffma2(ull& acc, ull a, ull b) {
    asm("fma.rn.f32x2 %0, %1, %2, %0;" : "+l"(acc) : "l"(a), "l"(b));
}

template <int K, int AP>
__device__ __forceinline__ void mma_tile(const float* __restrict__ As,
                                         const float* __restrict__ Ws,
                                         int tr8, int tc8, ull acc[8][4])
{
#pragma unroll 4
    for (int kk = 0; kk < K; kk++) {
        const ulonglong2* wp = reinterpret_cast<const ulonglong2*>(Ws + kk * 128 + tc8);
        ulonglong2 w01 = wp[0];
        ulonglong2 w23 = wp[1];
        ull ad[8];
#pragma unroll
        for (int i = 0; i < 8; i++) ad[i] = dup2(As[(tr8 + i) * AP + kk]);
#pragma unroll
        for (int i = 0; i < 8; i++) {
            ffma2(acc[i][0], ad[i], w01.x);
            ffma2(acc[i][1], ad[i], w01.y);
            ffma2(acc[i][2], ad[i], w23.x);
            ffma2(acc[i][3], ad[i], w23.y);
        }
    }
}
__device__ __forceinline__ void zero_acc(ull acc[8][4]) {
#pragma unroll
    for (int i = 0; i < 8; i++)
#pragma unroll
        for (int p = 0; p < 4; p++) acc[i][p] = 0ull;
}

// ---------------- tcgen05 helpers (compiled only on 'a' targets) ----------------
#if HAS_TCGEN05
__device__ __forceinline__ bool elect1() {
    uint32_t p;
    asm volatile("{\n\t.reg .pred p;\n\telect.sync _|p, 0xFFFFFFFF;\n\tselp.b32 %0,1,0,p;\n\t}" : "=r"(p));
    return p != 0;
}
__device__ __forceinline__ ull mkdesc(uint32_t addr) {
    // SW128 K-major: layout=2, version=1, SBO=64, LBO=1
    return 0x4000404000010000ull | ((ull)(addr >> 4) & 0x3FFFull);
}
__device__ __forceinline__ void mma_ss_f16(uint32_t d, ull ad, ull bd, uint32_t idesc, uint32_t acc) {
    asm volatile(
        "{\n\t.reg .pred p;\n\tsetp.ne.u32 p, %5, 0;\n\t"
        "tcgen05.mma.cta_group::1.kind::f16 [%0], %1, %2, %3, {%4,%4,%4,%4}, p;\n\t}"
        :: "r"(d), "l"(ad), "l"(bd), "r"(idesc), "r"(0u), "r"(acc) : "memory");
}
__device__ __forceinline__ void tc_commit(uint32_t mbar) {
    asm volatile("tcgen05.commit.cta_group::1.mbarrier::arrive::one.shared::cluster.b64 [%0];"
                 :: "r"(mbar) : "memory");
}
__device__ __forceinline__ void mbar_init(uint32_t a, uint32_t cnt) {
    asm volatile("mbarrier.init.shared.b64 [%0], %1;" :: "r"(a), "r"(cnt) : "memory");
}
__device__ __forceinline__ void mbar_wait(uint32_t a, uint32_t ph) {
    asm volatile(
        "{\n\t.reg .pred P;\n\tLW%=:\n\t"
        "mbarrier.try_wait.parity.acquire.cta.shared::cta.b64 P, [%0], %1;\n\t"
        "@!P bra LW%=;\n\t}"
        :: "r"(a), "r"(ph) : "memory");
}
#define TC_WAIT_LD()   asm volatile("tcgen05.wait::ld.sync.aligned;" ::: "memory")
#define TC_FENCE_B()   asm volatile("tcgen05.fence::before_thread_sync;" ::: "memory")
#define TC_FENCE_A()   asm volatile("tcgen05.fence::after_thread_sync;" ::: "memory")
#define FENCE_PROXY()  asm volatile("fence.proxy.async.shared::cta;" ::: "memory")

__device__ __forceinline__ void ldtm32(uint32_t* r, uint32_t a) {
    asm volatile(
        "tcgen05.ld.sync.aligned.32x32b.x32.b32 "
        "{%0,%1,%2,%3,%4,%5,%6,%7,%8,%9,%10,%11,%12,%13,%14,%15,"
        "%16,%17,%18,%19,%20,%21,%22,%23,%24,%25,%26,%27,%28,%29,%30,%31}, [%32];"
        : "=r"(r[0]), "=r"(r[1]), "=r"(r[2]), "=r"(r[3]), "=r"(r[4]), "=r"(r[5]), "=r"(r[6]), "=r"(r[7]),
          "=r"(r[8]), "=r"(r[9]), "=r"(r[10]), "=r"(r[11]), "=r"(r[12]), "=r"(r[13]), "=r"(r[14]), "=r"(r[15]),
          "=r"(r[16]), "=r"(r[17]), "=r"(r[18]), "=r"(r[19]), "=r"(r[20]), "=r"(r[21]), "=r"(r[22]), "=r"(r[23]),
          "=r"(r[24]), "=r"(r[25]), "=r"(r[26]), "=r"(r[27]), "=r"(r[28]), "=r"(r[29]), "=r"(r[30]), "=r"(r[31])
        : "r"(a));
}

// SW128 blocked-atom byte offset for bf16 element (row, col); nar = rows/8 atom-rows.
__device__ __forceinline__ uint32_t swz_bf16(int row, int col, int nar) {
    uint32_t b = (uint32_t)((row >> 3) + (col >> 6) * nar) * 1024u
               + (uint32_t)(row & 7) * 128u + (uint32_t)(col & 63) * 2u;
    return b ^ ((b >> 3) & 0x70u);
}

__device__ __forceinline__ void store_pair(char* ah, char* al, int row, int col, float v0, float v1) {
    uint32_t h;
    asm("cvt.rn.bf16x2.f32 %0, %1, %2;" : "=r"(h) : "f"(v1), "f"(v0));
    float h0 = __uint_as_float(h << 16);
    float h1 = __uint_as_float(h & 0xffff0000u);
    uint32_t l;
    asm("cvt.rn.bf16x2.f32 %0, %1, %2;" : "=r"(l) : "f"(v1 - h1), "f"(v0 - h0));
    uint32_t o = swz_bf16(row, col, 16);
    *(uint32_t*)(ah + o) = h;
    *(uint32_t*)(al + o) = l;
}
#endif  // HAS_TCGEN05

// ---------------- zero scratch ----------------
__global__ void k_zero() {
    size_t i = (size_t)blockIdx.x * blockDim.x + threadIdx.x;
    size_t stride = (size_t)gridDim.x * blockDim.x;
    const float4 z = make_float4(0.f, 0.f, 0.f, 0.f);
    for (size_t k = i; k < ((size_t)N_FLOW * D_H) / 4; k += stride) ((float4*)g_aggF)[k] = z;
    for (size_t k = i; k < ((size_t)N_FLOW * D_H) / 4; k += stride) ((float4*)g_agg2)[k] = z;
    for (size_t k = i; k < ((size_t)N_HOST * D_IN) / 4; k += stride) ((float4*)g_aggH)[k] = z;
    for (size_t k = i; k < (size_t)N_FLOW / 4; k += stride) ((float4*)g_cntF)[k] = z;
    for (size_t k = i; k < (size_t)N_HOST / 4; k += stride) ((float4*)g_cntH)[k] = z;
}

// ---------------- edge scatter ----------------
__global__ __launch_bounds__(256) void k_scatter(
    const float* __restrict__ feat, const int* __restrict__ src,
    const int* __restrict__ dst, float* __restrict__ agg,
    float* __restrict__ cnt, int E, int D)
{
    int lpe  = D >> 2;
    int eloc = threadIdx.x / lpe;
    int lane = threadIdx.x - eloc * lpe;
    int epb  = blockDim.x / lpe;
    int e = blockIdx.x * epb + eloc;
    if (e >= E) return;
    int s = __ldg(src + e);
    int d = __ldg(dst + e);
    float4 v = *(const float4*)(feat + (size_t)s * D + lane * 4);
    float* p = agg + (size_t)d * D + lane * 4;
    asm volatile("red.global.add.v4.f32 [%0], {%1,%2,%3,%4};"
                 :: "l"(p), "f"(v.x), "f"(v.y), "f"(v.z), "f"(v.w) : "memory");
    if (cnt != nullptr && lane == 0) atomicAdd(cnt + d, 1.0f);
}

// ---------------- dual small GEMM (FFMA2): tx0 = xh@Wa ; xr = xh@Wb ----------------
struct DualSmem {
    float Wa[64 * 128];
    float Wb[64 * 128];
    float Asf[128 * 68];
};

__global__ __launch_bounds__(256, 1) void k_dual(
    const float* __restrict__ xh,
    const float* __restrict__ Wla, const float* __restrict__ Wlb,
    float* __restrict__ Ca, float* __restrict__ Cb)
{
    DualSmem* S = reinterpret_cast<DualSmem*>(smem_raw);
    const int tid = threadIdx.x;
    for (int f = tid; f < 64 * 128 / 4; f += 256) {
        ((float4*)S->Wa)[f] = ((const float4*)Wla)[f];
        ((float4*)S->Wb)[f] = ((const float4*)Wlb)[f];
    }
    const int tr8 = (tid >> 4) * 8;
    const int tc8 = (tid & 15) * 8;

    const int NT = (N_HOST + 127) / 128;
    for (int tile = blockIdx.x; tile < NT; tile += gridDim.x) {
        const int row0 = tile * 128;
        __syncthreads();
        for (int f = tid; f < 2048; f += 256) {
            int r = f >> 4, cc = (f & 15) * 4;
            int gr = row0 + r;
            if (gr < N_HOST)
                *(float4*)(S->Asf + r * 68 + cc) = *(const float4*)(xh + (size_t)gr * 64 + cc);
        }
        __syncthreads();

        ull acc[8][4];
        zero_acc(acc);
        mma_tile<64, 68>(S->Asf, S->Wa, tr8, tc8, acc);
#pragma unroll
        for (int i = 0; i < 8; i++) {
            int gr = row0 + tr8 + i;
            if (gr >= N_HOST) continue;
            float2 v0 = *reinterpret_cast<float2*>(&acc[i][0]);
            float2 v1 = *reinterpret_cast<float2*>(&acc[i][1]);
            float2 v2 = *reinterpret_cast<float2*>(&acc[i][2]);
            float2 v3 = *reinterpret_cast<float2*>(&acc[i][3]);
            *(float4*)(Ca + (size_t)gr * 128 + tc8)     = make_float4(v0.x, v0.y, v1.x, v1.y);
            *(float4*)(Ca + (size_t)gr * 128 + tc8 + 4) = make_float4(v2.x, v2.y, v3.x, v3.y);
        }
        zero_acc(acc);
        mma_tile<64, 68>(S->Asf, S->Wb, tr8, tc8, acc);
#pragma unroll
        for (int i = 0; i < 8; i++) {
            int gr = row0 + tr8 + i;
            if (gr >= N_HOST) continue;
            float2 v0 = *reinterpret_cast<float2*>(&acc[i][0]);
            float2 v1 = *reinterpret_cast<float2*>(&acc[i][1]);
            float2 v2 = *reinterpret_cast<float2*>(&acc[i][2]);
            float2 v3 = *reinterpret_cast<float2*>(&acc[i][3]);
            *(float4*)(Cb + (size_t)gr * 128 + tc8)     = make_float4(v0.x, v0.y, v1.x, v1.y);
            *(float4*)(Cb + (size_t)gr * 128 + tc8 + 4) = make_float4(v2.x, v2.y, v3.x, v3.y);
        }
    }
}

// ---------------- fused host chain (FFMA2) ----------------
struct HostSmem {
    float Ws0[64 * 128];
    float Ws1[128 * 128];
    float Asf[128 * 68];
    float H[128 * 132];
};

__global__ __launch_bounds__(256, 1) void k_host(
    const float* __restrict__ aggH, const float* __restrict__ cntH,
    const float* __restrict__ xr,
    const float* __restrict__ W0l, const float* __restrict__ b0,
    const float* __restrict__ W1l,
    float* __restrict__ th1)
{
    HostSmem* S = reinterpret_cast<HostSmem*>(smem_raw);
    const int tid = threadIdx.x;
    for (int f = tid; f < 64 * 128 / 4; f += 256) ((float4*)S->Ws0)[f] = ((const float4*)W0l)[f];
    for (int f = tid; f < 128 * 128 / 4; f += 256) ((float4*)S->Ws1)[f] = ((const float4*)W1l)[f];

    const int tr8 = (tid >> 4) * 8;
    const int tc8 = (tid & 15) * 8;
    float b0r[8];
#pragma unroll
    for (int j = 0; j < 8; j++) b0r[j] = b0[tc8 + j];

    const int NT = (N_HOST + 127) / 128;
    for (int tile = blockIdx.x; tile < NT; tile += gridDim.x) {
        const int row0 = tile * 128;
        __syncthreads();
        for (int f = tid; f < 2048; f += 256) {
            int r = f >> 4, cc = (f & 15) * 4;
            int gr = row0 + r;
            if (gr < N_HOST) {
                float inv = 1.f / fmaxf(__ldg(cntH + gr), 1.f);
                float4 v = *(const float4*)(aggH + (size_t)gr * 64 + cc);
                v.x *= inv; v.y *= inv; v.z *= inv; v.w *= inv;
                *(float4*)(S->Asf + r * 68 + cc) = v;
            }
        }
        __syncthreads();

        ull acc[8][4];
        zero_acc(acc);
        mma_tile<64, 68>(S->Asf, S->Ws0, tr8, tc8, acc);
#pragma unroll
        for (int i = 0; i < 8; i++) {
            int gr = row0 + tr8 + i;
            if (gr >= N_HOST) continue;
            float4 p0 = *(const float4*)(xr + (size_t)gr * 128 + tc8);
            float4 p1 = *(const float4*)(xr + (size_t)gr * 128 + tc8 + 4);
            float pv[8] = {p0.x, p0.y, p0.z, p0.w, p1.x, p1.y, p1.z, p1.w};
#pragma unroll
            for (int p = 0; p < 4; p++) {
                float2 v = *reinterpret_cast<float2*>(&acc[i][p]);
                S->H[(tr8 + i) * 132 + tc8 + 2 * p]     = lrelu(v.x + pv[2 * p] + b0r[2 * p]);
                S->H[(tr8 + i) * 132 + tc8 + 2 * p + 1] = lrelu(v.y + pv[2 * p + 1] + b0r[2 * p + 1]);
            }
        }
        __syncthreads();

        zero_acc(acc);
        mma_tile<128, 132>(S->H, S->Ws1, tr8, tc8, acc);
#pragma unroll
        for (int i = 0; i < 8; i++) {
            int gr = row0 + tr8 + i;
            if (gr >= N_HOST) continue;
            float2 v0 = *reinterpret_cast<float2*>(&acc[i][0]);
            float2 v1 = *reinterpret_cast<float2*>(&acc[i][1]);
            float2 v2 = *reinterpret_cast<float2*>(&acc[i][2]);
            float2 v3 = *reinterpret_cast<float2*>(&acc[i][3]);
            *(float4*)(th1 + (size_t)gr * 128 + tc8)     = make_float4(v0.x, v0.y, v1.x, v1.y);
            *(float4*)(th1 + (size_t)gr * 128 + tc8 + 4) = make_float4(v2.x, v2.y, v3.x, v3.y);
        }
    }
}

// ================= flow chain =================
// tcgen05 smem layout
#define O_W0H 0
#define O_W0L 16384
#define O_W1H 32768
#define O_W1L 65536
#define O_WOH 98304
#define O_WOL 106496
#define O_AH  114688
#define O_AL  147456
#define O_STG 180224
#define O_B0  213504
#define O_B1  214016
#define O_BO  214528
#define O_MB  214784
#define O_TP  214816
#define TC_SMEM_USED 214824

// fallback (FFMA2) smem layout
struct FlowSmem {
    float Ws0[64 * 128];
    float Ws1[128 * 128];
    float Wso[128 * 32];
    float Asf[128 * 68];
    float H[128 * 132];
};

#define FLOW_SMEM_REQ 219136   // max(TC_SMEM_USED+1024, sizeof(FlowSmem)) rounded up

__global__ __launch_bounds__(256, 1)
void k_flow_tc(const float* __restrict__ xf,
               const float* __restrict__ aggF, const float* __restrict__ agg2,
               const float* __restrict__ cnt,
               const float* __restrict__ W0r, const float* __restrict__ b0,
               const float* __restrict__ W1r, const float* __restrict__ b1,
               const float* __restrict__ Wo,  const float* __restrict__ bo,
               float* __restrict__ out)
{
#if HAS_TCGEN05
    // ==================== tcgen05 path ====================
    const int tid = threadIdx.x;
    const int wid = tid >> 5;
    const int lane = tid & 31;

    uint32_t raw = smem_u32(smem_raw);
    uint32_t base = (raw + 1023u) & ~1023u;
    char* sp = smem_raw + (base - raw);

    char* pW0H = sp + O_W0H; char* pW0L = sp + O_W0L;
    char* pW1H = sp + O_W1H; char* pW1L = sp + O_W1L;
    char* pWOH = sp + O_WOH; char* pWOL = sp + O_WOL;
    char* pAH  = sp + O_AH;  char* pAL  = sp + O_AL;
    float* stg = (float*)(sp + O_STG);
    float* b0s = (float*)(sp + O_B0);
    float* b1s = (float*)(sp + O_B1);
    float* bos = (float*)(sp + O_BO);
    const uint32_t MB = base + O_MB;

    for (int i = tid; i < 128 * 128; i += 256) {
        int k = i >> 7, n = i & 127;
        float v = W1r[i];
        __nv_bfloat16 h = __float2bfloat16(v);
        __nv_bfloat16 l = __float2bfloat16(v - __bfloat162float(h));
        uint32_t o = swz_bf16(n, k, 16);
        *(__nv_bfloat16*)(pW1H + o) = h;
        *(__nv_bfloat16*)(pW1L + o) = l;
    }
    for (int i = tid; i < 64 * 128; i += 256) {
        int k = i >> 7, n = i & 127;
        float v = W0r[i];
        __nv_bfloat16 h = __float2bfloat16(v);
        __nv_bfloat16 l = __float2bfloat16(v - __bfloat162float(h));
        uint32_t o = swz_bf16(n, k, 16);
        *(__nv_bfloat16*)(pW0H + o) = h;
        *(__nv_bfloat16*)(pW0L + o) = l;
    }
    for (int i = tid; i < 128 * 32; i += 256) {
        int k = i >> 5, n = i & 31;
        float v = Wo[i];
        __nv_bfloat16 h = __float2bfloat16(v);
        __nv_bfloat16 l = __float2bfloat16(v - __bfloat162float(h));
        uint32_t o = swz_bf16(n, k, 4);
        *(__nv_bfloat16*)(pWOH + o) = h;
        *(__nv_bfloat16*)(pWOL + o) = l;
    }
    for (int i = tid; i < 128; i += 256) { b0s[i] = b0[i]; b1s[i] = b1[i]; }
    if (tid < 32) bos[tid] = bo[tid];
    if (tid == 0) { mbar_init(MB, 1); mbar_init(MB + 8, 1); mbar_init(MB + 16, 1); }
    if (wid == 0) {
        asm volatile("tcgen05.alloc.cta_group::1.sync.aligned.shared::cta.b32 [%0], %1;"
                     :: "r"(base + O_TP), "r"(512) : "memory");
    }
    FENCE_PROXY();
    __syncthreads();
    uint32_t tmem;
    asm volatile("ld.shared.b32 %0, [%1];" : "=r"(tmem) : "r"(base + O_TP));

    const ull dAH = mkdesc(base + O_AH),  dAL = mkdesc(base + O_AL);
    const ull dW0H = mkdesc(base + O_W0H), dW0L = mkdesc(base + O_W0L);
    const ull dW1H = mkdesc(base + O_W1H), dW1L = mkdesc(base + O_W1L);
    const ull dWOH = mkdesc(base + O_WOH), dWOL = mkdesc(base + O_WOL);
    const uint32_t idesc128 = 0x8200490u;
    const uint32_t idesc32  = 0x8080490u;

    const int sub = wid & 3, half = wid >> 2;
    const int r = sub * 32 + lane;
    const uint32_t tmoff = (uint32_t)sub << 21;

    const int NT = (N_FLOW + 127) / 128;
    int it = 0;
    for (int tile = blockIdx.x; tile < NT; tile += gridDim.x, ++it) {
        const int row0 = tile << 7;
        const int par = it & 1;
        __syncthreads();

        {
            int xrow = tid >> 1, c0x = (tid & 1) * 32;
            int g = row0 + xrow;
            if (g < N_FLOW) {
                const float4* src = (const float4*)(xf + (size_t)g * 64 + c0x);
#pragma unroll
                for (int i = 0; i < 8; i++) {
                    float4 v = src[i];
                    int c = c0x + i * 4;
                    store_pair(pAH, pAL, xrow, c,     v.x, v.y);
                    store_pair(pAH, pAL, xrow, c + 2, v.z, v.w);
                }
            }
        }
        float invF = 0.f;
        { int g = row0 + r; if (g < N_FLOW) invF = 1.f / fmaxf(__ldg(cnt + g), 1.f); }
        FENCE_PROXY();
        __syncthreads();

        if (wid == 0 && elect1()) {
            const int AO[4] = {0, 2, 4, 6};
#pragma unroll
            for (int s = 0; s < 4; s++) mma_ss_f16(tmem, dAH + AO[s], dW0H + AO[s], idesc128, s > 0);
#pragma unroll
            for (int s = 0; s < 4; s++) mma_ss_f16(tmem, dAH + AO[s], dW0L + AO[s], idesc128, 1);
#pragma unroll
            for (int s = 0; s < 4; s++) mma_ss_f16(tmem, dAL + AO[s], dW0H + AO[s], idesc128, 1);
            tc_commit(MB);
        }
        mbar_wait(MB, par);
        TC_FENCE_A();

        for (int k2 = 0; k2 < 2; k2++) {
            __syncthreads();
            for (int i = 0; i < 8; i++) {
                int f = tid + i * 256;
                int r2 = f >> 4, c4 = (f & 15) * 4;
                int g2 = row0 + r2;
                float4 v = (g2 < N_FLOW)
                    ? *(const float4*)(aggF + (size_t)g2 * 128 + k2 * 64 + c4)
                    : make_float4(0.f, 0.f, 0.f, 0.f);
                float* d = stg + r2 * 65 + c4;
                d[0] = v.x; d[1] = v.y; d[2] = v.z; d[3] = v.w;
            }
            __syncthreads();
            int c0 = k2 * 64 + half * 32;
            uint32_t dr[32];
            ldtm32(dr, tmem + c0 + tmoff);
            TC_WAIT_LD();
            if (row0 + r < N_FLOW) {
                const float* sr = stg + r * 65 + half * 32;
#pragma unroll
                for (int j = 0; j < 32; j += 2) {
                    float v0 = lrelu(__uint_as_float(dr[j])     + sr[j] * invF     + b0s[c0 + j]);
                    float v1 = lrelu(__uint_as_float(dr[j + 1]) + sr[j + 1] * invF + b0s[c0 + j + 1]);
                    store_pair(pAH, pAL, r, c0 + j, v0, v1);
                }
            }
            TC_FENCE_B();
        }
        FENCE_PROXY();
        __syncthreads();

        if (wid == 0 && elect1()) {
            const int AO[8] = {0, 2, 4, 6, 1024, 1026, 1028, 1030};
#pragma unroll
            for (int s = 0; s < 8; s++) mma_ss_f16(tmem, dAH + AO[s], dW1H + AO[s], idesc128, s > 0);
#pragma unroll
            for (int s = 0; s < 8; s++) mma_ss_f16(tmem, dAH + AO[s], dW1L + AO[s], idesc128, 1);
#pragma unroll
            for (int s = 0; s < 8; s++) mma_ss_f16(tmem, dAL + AO[s], dW1H + AO[s], idesc128, 1);
            tc_commit(MB + 8);
        }
        mbar_wait(MB + 8, par);
        TC_FENCE_A();

        for (int k2 = 0; k2 < 2; k2++) {
            __syncthreads();
            for (int i = 0; i < 8; i++) {
                int f = tid + i * 256;
                int r2 = f >> 4, c4 = (f & 15) * 4;
                int g2 = row0 + r2;
                float4 v = (g2 < N_FLOW)
                    ? *(const float4*)(agg2 + (size_t)g2 * 128 + k2 * 64 + c4)
                    : make_float4(0.f, 0.f, 0.f, 0.f);
                float* d = stg + r2 * 65 + c4;
                d[0] = v.x; d[1] = v.y; d[2] = v.z; d[3] = v.w;
            }
            __syncthreads();
            int c0 = k2 * 64 + half * 32;
            uint32_t dr[32];
            ldtm32(dr, tmem + c0 + tmoff);
            TC_WAIT_LD();
            if (row0 + r < N_FLOW) {
                const float* sr = stg + r * 65 + half * 32;
#pragma unroll
                for (int j = 0; j < 32; j += 2) {
                    float v0 = lrelu(__uint_as_float(dr[j])     + sr[j] * invF     + b1s[c0 + j]);
                    float v1 = lrelu(__uint_as_float(dr[j + 1]) + sr[j + 1] * invF + b1s[c0 + j + 1]);
                    store_pair(pAH, pAL, r, c0 + j, v0, v1);
                }
            }
            TC_FENCE_B();
        }
        FENCE_PROXY();
        __syncthreads();

        if (wid == 0 && elect1()) {
            const int AO[8] = {0, 2, 4, 6, 1024, 1026, 1028, 1030};
            const int BO[8] = {0, 2, 4, 6, 256, 258, 260, 262};
#pragma unroll
            for (int s = 0; s < 8; s++) mma_ss_f16(tmem, dAH + AO[s], dWOH + BO[s], idesc32, s > 0);
#pragma unroll
            for (int s = 0; s < 8; s++) mma_ss_f16(tmem, dAH + AO[s], dWOL + BO[s], idesc32, 1);
#pragma unroll
            for (int s = 0; s < 8; s++) mma_ss_f16(tmem, dAL + AO[s], dWOH + BO[s], idesc32, 1);
            tc_commit(MB + 16);
        }
        mbar_wait(MB + 16, par);
        TC_FENCE_A();

        if (wid < 4) {
            uint32_t dr[32];
            ldtm32(dr, tmem + tmoff);
            TC_WAIT_LD();
            int g = row0 + r;
            if (g < N_FLOW) {
                float* op = out + (size_t)g * 32;
#pragma unroll
                for (int c = 0; c < 32; c += 4) {
                    float4 o = make_float4(__uint_as_float(dr[c])     + bos[c],
                                           __uint_as_float(dr[c + 1]) + bos[c + 1],
                                           __uint_as_float(dr[c + 2]) + bos[c + 2],
                                           __uint_as_float(dr[c + 3]) + bos[c + 3]);
                    *(float4*)(op + c) = o;
                }
            }
            TC_FENCE_B();
        }
    }

    __syncthreads();
    if (wid == 0) {
        asm volatile("tcgen05.relinquish_alloc_permit.cta_group::1.sync.aligned;");
        asm volatile("tcgen05.dealloc.cta_group::1.sync.aligned.b32 %0, %1;" :: "r"(tmem), "r"(512));
    }
#else
    // ==================== FFMA2 fallback path ====================
    FlowSmem* S = reinterpret_cast<FlowSmem*>(smem_raw);
    const int tid = threadIdx.x;
    for (int f = tid; f < 64 * 128 / 4; f += 256) ((float4*)S->Ws0)[f] = ((const float4*)W0r)[f];
    for (int f = tid; f < 128 * 128 / 4; f += 256) ((float4*)S->Ws1)[f] = ((const float4*)W1r)[f];
    for (int f = tid; f < 128 * 32 / 4; f += 256) ((float4*)S->Wso)[f] = ((const float4*)Wo)[f];

    const int tr8 = (tid >> 4) * 8;
    const int tc8 = (tid & 15) * 8;
    float b0r[8], b1r[8];
#pragma unroll
    for (int j = 0; j < 8; j++) { b0r[j] = b0[tc8 + j]; b1r[j] = b1[tc8 + j]; }
    const int r4 = (tid >> 3) * 4;
    const int c4 = (tid & 7) * 4;
    float bor[4];
#pragma unroll
    for (int j = 0; j < 4; j++) bor[j] = bo[c4 + j];

    const int NT = (N_FLOW + 127) / 128;
    for (int tile = blockIdx.x; tile < NT; tile += gridDim.x) {
        const int row0 = tile * 128;
        __syncthreads();
        for (int f = tid; f < 2048; f += 256) {
            int r = f >> 4, cc = (f & 15) * 4;
            int gr = row0 + r;
            if (gr < N_FLOW)
                *(float4*)(S->Asf + r * 68 + cc) = *(const float4*)(xf + (size_t)gr * 64 + cc);
        }
        __syncthreads();

        ull acc[8][4];
        zero_acc(acc);
        mma_tile<64, 68>(S->Asf, S->Ws0, tr8, tc8, acc);
#pragma unroll
        for (int i = 0; i < 8; i++) {
            int gr = row0 + tr8 + i;
            if (gr >= N_FLOW) continue;
            float inv = 1.f / fmaxf(__ldg(cnt + gr), 1.f);
            float4 p0 = *(const float4*)(aggF + (size_t)gr * 128 + tc8);
            float4 p1 = *(const float4*)(aggF + (size_t)gr * 128 + tc8 + 4);
            float pv[8] = {p0.x, p0.y, p0.z, p0.w, p1.x, p1.y, p1.z, p1.w};
#pragma unroll
            for (int p = 0; p < 4; p++) {
                float2 v = *reinterpret_cast<float2*>(&acc[i][p]);
                S->H[(tr8 + i) * 132 + tc8 + 2 * p]     = lrelu(v.x + pv[2 * p] * inv + b0r[2 * p]);
                S->H[(tr8 + i) * 132 + tc8 + 2 * p + 1] = lrelu(v.y + pv[2 * p + 1] * inv + b0r[2 * p + 1]);
            }
        }
        __syncthreads();

        zero_acc(acc);
        mma_tile<128, 132>(S->H, S->Ws1, tr8, tc8, acc);
        __syncthreads();
#pragma unroll
        for (int i = 0; i < 8; i++) {
            int gr = row0 + tr8 + i;
            if (gr >= N_FLOW) continue;
            float inv = 1.f / fmaxf(__ldg(cnt + gr), 1.f);
            float4 p0 = *(const float4*)(agg2 + (size_t)gr * 128 + tc8);
            float4 p1 = *(const float4*)(agg2 + (size_t)gr * 128 + tc8 + 4);
            float pv[8] = {p0.x, p0.y, p0.z, p0.w, p1.x, p1.y, p1.z, p1.w};
#pragma unroll
            for (int p = 0; p < 4; p++) {
                float2 v = *reinterpret_cast<float2*>(&acc[i][p]);
                S->H[(tr8 + i) * 132 + tc8 + 2 * p]     = lrelu(v.x + pv[2 * p] * inv + b1r[2 * p]);
                S->H[(tr8 + i) * 132 + tc8 + 2 * p + 1] = lrelu(v.y + pv[2 * p + 1] * inv + b1r[2 * p + 1]);
            }
        }
        __syncthreads();

        ull acc3[4][2];
#pragma unroll
        for (int i = 0; i < 4; i++) { acc3[i][0] = 0ull; acc3[i][1] = 0ull; }
#pragma unroll 4
        for (int kk = 0; kk < 128; kk++) {
            ulonglong2 w = *reinterpret_cast<const ulonglong2*>(S->Wso + kk * 32 + c4);
#pragma unroll
            for (int i = 0; i < 4; i++) {
                ull ad = dup2(S->H[(r4 + i) * 132 + kk]);
                ffma2(acc3[i][0], ad, w.x);
                ffma2(acc3[i][1], ad, w.y);
            }
        }
#pragma unroll
        for (int i = 0; i < 4; i++) {
            int gr = row0 + r4 + i;
            if (gr >= N_FLOW) continue;
            float2 v0 = *reinterpret_cast<float2*>(&acc3[i][0]);
            float2 v1 = *reinterpret_cast<float2*>(&acc3[i][1]);
            *(float4*)(out + (size_t)gr * 32 + c4) =
                make_float4(v0.x + bor[0], v0.y + bor[1], v1.x + bor[2], v1.y + bor[3]);
        }
    }
#endif
}

// ---------------- host launcher ----------------
extern "C" void kernel_launch(void* const* d_in, const int* in_sizes, int n_in,
                              void* d_out, int out_size)
{
    const float* x_host  = (const float*)d_in[0];
    const float* x_flow  = (const float*)d_in[1];
    const int*   src_hf  = (const int*)d_in[2];
    const int*   dst_hf  = (const int*)d_in[3];
    const int*   src_fh  = (const int*)d_in[4];
    const int*   dst_fh  = (const int*)d_in[5];
    const float* W0_hf_l = (const float*)d_in[6];
    const float* W0_hf_r = (const float*)d_in[7];
    const float* b0_hf   = (const float*)d_in[8];
    const float* W0_fh_l = (const float*)d_in[9];
    const float* W0_fh_r = (const float*)d_in[10];
    const float* b0_fh   = (const float*)d_in[11];
    const float* W1_hf_l = (const float*)d_in[12];
    const float* W1_hf_r = (const float*)d_in[13];
    const float* b1_hf   = (const float*)d_in[14];
    // d_in[15..17] unused (g_host discarded)
    const float* W_out   = (const float*)d_in[18];
    const float* b_out   = (const float*)d_in[19];
    float* out = (float*)d_out;

    float *tx0, *xr, *aggF, *cntF, *aggH, *cntH, *th1, *agg2;
    cudaGetSymbolAddress((void**)&tx0,  g_tx0);
    cudaGetSymbolAddress((void**)&xr,   g_xr);
    cudaGetSymbolAddress((void**)&aggF, g_aggF);
    cudaGetSymbolAddress((void**)&cntF, g_cntF);
    cudaGetSymbolAddress((void**)&aggH, g_aggH);
    cudaGetSymbolAddress((void**)&cntH, g_cntH);
    cudaGetSymbolAddress((void**)&th1,  g_th1);
    cudaGetSymbolAddress((void**)&agg2, g_agg2);

    cudaFuncSetAttribute(k_dual, cudaFuncAttributeMaxDynamicSharedMemorySize, (int)sizeof(DualSmem));
    cudaFuncSetAttribute(k_host, cudaFuncAttributeMaxDynamicSharedMemorySize, (int)sizeof(HostSmem));
    cudaFuncSetAttribute(k_flow_tc, cudaFuncAttributeMaxDynamicSharedMemorySize, FLOW_SMEM_REQ);

    // 1. zero accumulators
    k_zero<<<2048, 256>>>();

    // 2. tx0 = x_host @ W0_hf_l ; xr = x_host @ W0_fh_r
    k_dual<<<157, 256, sizeof(DualSmem)>>>(x_host, W0_hf_l, W0_fh_r, tx0, xr);

    // 3. aggH[dst_fh] += x_flow[src_fh]; cntH++
    k_scatter<<<(NE + 15) / 16, 256>>>(x_flow, src_fh, dst_fh, aggH, cntH, NE, D_IN);

    // 4. aggF[dst_hf] += tx0[src_hf]; cntF++
    k_scatter<<<(NE + 7) / 8, 256>>>(tx0, src_hf, dst_hf, aggF, cntF, NE, D_H);

    // 5. fused host chain -> th1
    k_host<<<152, 256, sizeof(HostSmem)>>>(aggH, cntH, xr, W0_fh_l, b0_fh, W1_hf_l, th1);

    // 6. agg2[dst_hf] += th1[src_hf]
    k_scatter<<<(NE + 7) / 8, 256>>>(th1, src_hf, dst_hf, agg2, nullptr, NE, D_H);

    // 7. fused flow chain -> out (tcgen05 if available, FFMA2 otherwise)
    k_flow_tc<<<148, 256, FLOW_SMEM_REQ>>>(x_flow, aggF, agg2, cntF,
                                           W0_hf_r, b0_hf, W1_hf_r, b1_hf,
                                           W_out, b_out, out);
}

// round 5
// speedup vs baseline: 1.8635x; 1.1967x over previous
#include <cuda_runtime.h>
#include <cuda_bf16.h>
#include <cstdint>

// Problem constants
#define N_HOST 20000
#define N_FLOW 200000
#define NE     600000
#define D_IN   64
#define D_H    128
#define D_OUT  32

typedef unsigned long long ull;

#if defined(__CUDA_ARCH_FEAT_SM103_ALL) || defined(__CUDA_ARCH_FEAT_SM100_ALL) || defined(__CUDA_ARCH_FEAT_SM101_ALL)
#define HAS_TCGEN05 1
#else
#define HAS_TCGEN05 0
#endif

// ---------------- scratch ----------------
__device__ float g_xr   [(size_t)N_HOST * D_H];   // x_host @ W0_fh_r
__device__ float g_aggX [(size_t)N_FLOW * D_IN];  // scatter of x_host over hf edges (64-dim)
__device__ float g_cntF [N_FLOW];
__device__ float g_aggH [(size_t)N_HOST * D_IN];  // scatter of x_flow over fh edges
__device__ float g_cntH [N_HOST];
__device__ float g_th1  [(size_t)N_HOST * D_H];   // h_host @ W1_hf_l
__device__ float g_agg2 [(size_t)N_FLOW * D_H];   // scatter of th1 over hf edges

extern __shared__ char smem_raw[];

// ---------------- generic helpers ----------------
__device__ __forceinline__ float lrelu(float v) { return v > 0.f ? v : 0.01f * v; }

__device__ __forceinline__ uint32_t smem_u32(const void* p) {
    uint32_t a;
    asm("{ .reg .u64 t; cvta.to.shared.u64 t, %1; cvt.u32.u64 %0, t; }" : "=r"(a) : "l"(p));
    return a;
}

// ---------------- f32x2 packed-FMA helpers ----------------
__device__ __forceinline__ ull dup2(float x) {
    ull r; asm("mov.b64 %0, {%1, %1};" : "=l"(r) : "f"(x)); return r;
}
__device__ __forceinline__ void ffma2(ull& acc, ull a, ull b) {
    asm("fma.rn.f32x2 %0, %1, %2, %0;" : "+l"(acc) : "l"(a), "l"(b));
}

template <int K, int AP>
__device__ __forceinline__ void mma_tile(const float* __restrict__ As,
                                         const float* __restrict__ Ws,
                                         int tr8, int tc8, ull acc[8][4])
{
#pragma unroll 4
    for (int kk = 0; kk < K; kk++) {
        const ulonglong2* wp = reinterpret_cast<const ulonglong2*>(Ws + kk * 128 + tc8);
        ulonglong2 w01 = wp[0];
        ulonglong2 w23 = wp[1];
        ull ad[8];
#pragma unroll
        for (int i = 0; i < 8; i++) ad[i] = dup2(As[(tr8 + i) * AP + kk]);
#pragma unroll
        for (int i = 0; i < 8; i++) {
            ffma2(acc[i][0], ad[i], w01.x);
            ffma2(acc[i][1], ad[i], w01.y);
            ffma2(acc[i][2], ad[i], w23.x);
            ffma2(acc[i][3], ad[i], w23.y);
        }
    }
}
__device__ __forceinline__ void zero_acc(ull acc[8][4]) {
#pragma unroll
    for (int i = 0; i < 8; i++)
#pragma unroll
        for (int p = 0; p < 4; p++) acc[i][p] = 0ull;
}

// ---------------- tcgen05 helpers ----------------
#if HAS_TCGEN05
__device__ __forceinline__ bool elect1() {
    uint32_t p;
    asm volatile("{\n\t.reg .pred p;\n\telect.sync _|p, 0xFFFFFFFF;\n\tselp.b32 %0,1,0,p;\n\t}" : "=r"(p));
    return p != 0;
}
__device__ __forceinline__ ull mkdesc(uint32_t addr) {
    return 0x4000404000010000ull | ((ull)(addr >> 4) & 0x3FFFull);
}
__device__ __forceinline__ void mma_ss_f16(uint32_t d, ull ad, ull bd, uint32_t idesc, uint32_t acc) {
    asm volatile(
        "{\n\t.reg .pred p;\n\tsetp.ne.u32 p, %5, 0;\n\t"
        "tcgen05.mma.cta_group::1.kind::f16 [%0], %1, %2, %3, {%4,%4,%4,%4}, p;\n\t}"
        :: "r"(d), "l"(ad), "l"(bd), "r"(idesc), "r"(0u), "r"(acc) : "memory");
}
__device__ __forceinline__ void tc_commit(uint32_t mbar) {
    asm volatile("tcgen05.commit.cta_group::1.mbarrier::arrive::one.shared::cluster.b64 [%0];"
                 :: "r"(mbar) : "memory");
}
__device__ __forceinline__ void mbar_init(uint32_t a, uint32_t cnt) {
    asm volatile("mbarrier.init.shared.b64 [%0], %1;" :: "r"(a), "r"(cnt) : "memory");
}
__device__ __forceinline__ void mbar_wait(uint32_t a, uint32_t ph) {
    asm volatile(
        "{\n\t.reg .pred P;\n\tLW%=:\n\t"
        "mbarrier.try_wait.parity.acquire.cta.shared::cta.b64 P, [%0], %1;\n\t"
        "@!P bra LW%=;\n\t}"
        :: "r"(a), "r"(ph) : "memory");
}
#define TC_WAIT_LD()   asm volatile("tcgen05.wait::ld.sync.aligned;" ::: "memory")
#define TC_FENCE_B()   asm volatile("tcgen05.fence::before_thread_sync;" ::: "memory")
#define TC_FENCE_A()   asm volatile("tcgen05.fence::after_thread_sync;" ::: "memory")
#define FENCE_PROXY()  asm volatile("fence.proxy.async.shared::cta;" ::: "memory")

__device__ __forceinline__ void ldtm32(uint32_t* r, uint32_t a) {
    asm volatile(
        "tcgen05.ld.sync.aligned.32x32b.x32.b32 "
        "{%0,%1,%2,%3,%4,%5,%6,%7,%8,%9,%10,%11,%12,%13,%14,%15,"
        "%16,%17,%18,%19,%20,%21,%22,%23,%24,%25,%26,%27,%28,%29,%30,%31}, [%32];"
        : "=r"(r[0]), "=r"(r[1]), "=r"(r[2]), "=r"(r[3]), "=r"(r[4]), "=r"(r[5]), "=r"(r[6]), "=r"(r[7]),
          "=r"(r[8]), "=r"(r[9]), "=r"(r[10]), "=r"(r[11]), "=r"(r[12]), "=r"(r[13]), "=r"(r[14]), "=r"(r[15]),
          "=r"(r[16]), "=r"(r[17]), "=r"(r[18]), "=r"(r[19]), "=r"(r[20]), "=r"(r[21]), "=r"(r[22]), "=r"(r[23]),
          "=r"(r[24]), "=r"(r[25]), "=r"(r[26]), "=r"(r[27]), "=r"(r[28]), "=r"(r[29]), "=r"(r[30]), "=r"(r[31])
        : "r"(a));
}

__device__ __forceinline__ uint32_t swz_bf16(int row, int col, int nar) {
    uint32_t b = (uint32_t)((row >> 3) + (col >> 6) * nar) * 1024u
               + (uint32_t)(row & 7) * 128u + (uint32_t)(col & 63) * 2u;
    return b ^ ((b >> 3) & 0x70u);
}

__device__ __forceinline__ void store_pair(char* ah, char* al, int row, int col, float v0, float v1) {
    uint32_t h;
    asm("cvt.rn.bf16x2.f32 %0, %1, %2;" : "=r"(h) : "f"(v1), "f"(v0));
    float h0 = __uint_as_float(h << 16);
    float h1 = __uint_as_float(h & 0xffff0000u);
    uint32_t l;
    asm("cvt.rn.bf16x2.f32 %0, %1, %2;" : "=r"(l) : "f"(v1 - h1), "f"(v0 - h0));
    uint32_t o = swz_bf16(row, col, 16);
    *(uint32_t*)(ah + o) = h;
    *(uint32_t*)(al + o) = l;
}
#endif  // HAS_TCGEN05

// ---------------- zero scratch ----------------
__global__ void k_zero() {
    size_t i = (size_t)blockIdx.x * blockDim.x + threadIdx.x;
    size_t stride = (size_t)gridDim.x * blockDim.x;
    const float4 z = make_float4(0.f, 0.f, 0.f, 0.f);
    for (size_t k = i; k < ((size_t)N_FLOW * D_IN) / 4; k += stride) ((float4*)g_aggX)[k] = z;
    for (size_t k = i; k < ((size_t)N_FLOW * D_H) / 4; k += stride) ((float4*)g_agg2)[k] = z;
    for (size_t k = i; k < ((size_t)N_HOST * D_IN) / 4; k += stride) ((float4*)g_aggH)[k] = z;
    for (size_t k = i; k < (size_t)N_FLOW / 4; k += stride) ((float4*)g_cntF)[k] = z;
    for (size_t k = i; k < (size_t)N_HOST / 4; k += stride) ((float4*)g_cntH)[k] = z;
}

// ---------------- edge scatter ----------------
__global__ __launch_bounds__(256) void k_scatter(
    const float* __restrict__ feat, const int* __restrict__ src,
    const int* __restrict__ dst, float* __restrict__ agg,
    float* __restrict__ cnt, int E, int D)
{
    int lpe  = D >> 2;
    int eloc = threadIdx.x / lpe;
    int lane = threadIdx.x - eloc * lpe;
    int epb  = blockDim.x / lpe;
    int e = blockIdx.x * epb + eloc;
    if (e >= E) return;
    int s = __ldg(src + e);
    int d = __ldg(dst + e);
    float4 v = *(const float4*)(feat + (size_t)s * D + lane * 4);
    float* p = agg + (size_t)d * D + lane * 4;
    asm volatile("red.global.add.v4.f32 [%0], {%1,%2,%3,%4};"
                 :: "l"(p), "f"(v.x), "f"(v.y), "f"(v.z), "f"(v.w) : "memory");
    if (cnt != nullptr && lane == 0) atomicAdd(cnt + d, 1.0f);
}

// ---------------- single small GEMM (FFMA2): xr = x_host @ W ----------------
struct XrSmem {
    float W[64 * 128];
    float Asf[128 * 68];
};

__global__ __launch_bounds__(256, 1) void k_xr(
    const float* __restrict__ xh, const float* __restrict__ Wg,
    float* __restrict__ C)
{
    XrSmem* S = reinterpret_cast<XrSmem*>(smem_raw);
    const int tid = threadIdx.x;
    for (int f = tid; f < 64 * 128 / 4; f += 256) ((float4*)S->W)[f] = ((const float4*)Wg)[f];
    const int tr8 = (tid >> 4) * 8;
    const int tc8 = (tid & 15) * 8;

    const int NT = (N_HOST + 127) / 128;
    for (int tile = blockIdx.x; tile < NT; tile += gridDim.x) {
        const int row0 = tile * 128;
        __syncthreads();
        for (int f = tid; f < 2048; f += 256) {
            int r = f >> 4, cc = (f & 15) * 4;
            int gr = row0 + r;
            if (gr < N_HOST)
                *(float4*)(S->Asf + r * 68 + cc) = *(const float4*)(xh + (size_t)gr * 64 + cc);
        }
        __syncthreads();

        ull acc[8][4];
        zero_acc(acc);
        mma_tile<64, 68>(S->Asf, S->W, tr8, tc8, acc);
#pragma unroll
        for (int i = 0; i < 8; i++) {
            int gr = row0 + tr8 + i;
            if (gr >= N_HOST) continue;
            float2 v0 = *reinterpret_cast<float2*>(&acc[i][0]);
            float2 v1 = *reinterpret_cast<float2*>(&acc[i][1]);
            float2 v2 = *reinterpret_cast<float2*>(&acc[i][2]);
            float2 v3 = *reinterpret_cast<float2*>(&acc[i][3]);
            *(float4*)(C + (size_t)gr * 128 + tc8)     = make_float4(v0.x, v0.y, v1.x, v1.y);
            *(float4*)(C + (size_t)gr * 128 + tc8 + 4) = make_float4(v2.x, v2.y, v3.x, v3.y);
        }
    }
}

// ---------------- fused host chain (FFMA2) ----------------
struct HostSmem {
    float Ws0[64 * 128];
    float Ws1[128 * 128];
    float Asf[128 * 68];
    float H[128 * 132];
};

__global__ __launch_bounds__(256, 1) void k_host(
    const float* __restrict__ aggH, const float* __restrict__ cntH,
    const float* __restrict__ xr,
    const float* __restrict__ W0l, const float* __restrict__ b0,
    const float* __restrict__ W1l,
    float* __restrict__ th1)
{
    HostSmem* S = reinterpret_cast<HostSmem*>(smem_raw);
    const int tid = threadIdx.x;
    for (int f = tid; f < 64 * 128 / 4; f += 256) ((float4*)S->Ws0)[f] = ((const float4*)W0l)[f];
    for (int f = tid; f < 128 * 128 / 4; f += 256) ((float4*)S->Ws1)[f] = ((const float4*)W1l)[f];

    const int tr8 = (tid >> 4) * 8;
    const int tc8 = (tid & 15) * 8;
    float b0r[8];
#pragma unroll
    for (int j = 0; j < 8; j++) b0r[j] = b0[tc8 + j];

    const int NT = (N_HOST + 127) / 128;
    for (int tile = blockIdx.x; tile < NT; tile += gridDim.x) {
        const int row0 = tile * 128;
        __syncthreads();
        for (int f = tid; f < 2048; f += 256) {
            int r = f >> 4, cc = (f & 15) * 4;
            int gr = row0 + r;
            if (gr < N_HOST) {
                float inv = 1.f / fmaxf(__ldg(cntH + gr), 1.f);
                float4 v = *(const float4*)(aggH + (size_t)gr * 64 + cc);
                v.x *= inv; v.y *= inv; v.z *= inv; v.w *= inv;
                *(float4*)(S->Asf + r * 68 + cc) = v;
            }
        }
        __syncthreads();

        ull acc[8][4];
        zero_acc(acc);
        mma_tile<64, 68>(S->Asf, S->Ws0, tr8, tc8, acc);
#pragma unroll
        for (int i = 0; i < 8; i++) {
            int gr = row0 + tr8 + i;
            if (gr >= N_HOST) continue;
            float4 p0 = *(const float4*)(xr + (size_t)gr * 128 + tc8);
            float4 p1 = *(const float4*)(xr + (size_t)gr * 128 + tc8 + 4);
            float pv[8] = {p0.x, p0.y, p0.z, p0.w, p1.x, p1.y, p1.z, p1.w};
#pragma unroll
            for (int p = 0; p < 4; p++) {
                float2 v = *reinterpret_cast<float2*>(&acc[i][p]);
                S->H[(tr8 + i) * 132 + tc8 + 2 * p]     = lrelu(v.x + pv[2 * p] + b0r[2 * p]);
                S->H[(tr8 + i) * 132 + tc8 + 2 * p + 1] = lrelu(v.y + pv[2 * p + 1] + b0r[2 * p + 1]);
            }
        }
        __syncthreads();

        zero_acc(acc);
        mma_tile<128, 132>(S->H, S->Ws1, tr8, tc8, acc);
#pragma unroll
        for (int i = 0; i < 8; i++) {
            int gr = row0 + tr8 + i;
            if (gr >= N_HOST) continue;
            float2 v0 = *reinterpret_cast<float2*>(&acc[i][0]);
            float2 v1 = *reinterpret_cast<float2*>(&acc[i][1]);
            float2 v2 = *reinterpret_cast<float2*>(&acc[i][2]);
            float2 v3 = *reinterpret_cast<float2*>(&acc[i][3]);
            *(float4*)(th1 + (size_t)gr * 128 + tc8)     = make_float4(v0.x, v0.y, v1.x, v1.y);
            *(float4*)(th1 + (size_t)gr * 128 + tc8 + 4) = make_float4(v2.x, v2.y, v3.x, v3.y);
        }
    }
}

// ================= flow chain =================
// tcgen05 smem layout (bytes from 1024-aligned base)
#define O_W01H 0
#define O_W01L 32768
#define O_W1H  65536
#define O_W1L  98304
#define O_WOH  131072
#define O_WOL  139264
#define O_AH   147456
#define O_AL   180224
#define O_B0   212992
#define O_B1   213504
#define O_BO   214016
#define O_MB   214144
#define O_TP   214176
#define TC_SMEM_USED 214184

#define FLOW_SMEM_REQ 231936   // covers both paths

__global__ __launch_bounds__(256, 1)
void k_flow_tc(const float* __restrict__ xf,
               const float* __restrict__ aggX, const float* __restrict__ agg2,
               const float* __restrict__ cnt,
               const float* __restrict__ W0r, const float* __restrict__ W0l,
               const float* __restrict__ b0,
               const float* __restrict__ W1r, const float* __restrict__ b1,
               const float* __restrict__ Wo,  const float* __restrict__ bo,
               float* __restrict__ out)
{
#if HAS_TCGEN05
    // ==================== tcgen05 path ====================
    const int tid = threadIdx.x;
    const int wid = tid >> 5;
    const int lane = tid & 31;

    uint32_t raw = smem_u32(smem_raw);
    uint32_t base = (raw + 1023u) & ~1023u;
    char* sp = smem_raw + (base - raw);

    char* pW01H = sp + O_W01H; char* pW01L = sp + O_W01L;
    char* pW1H  = sp + O_W1H;  char* pW1L  = sp + O_W1L;
    char* pWOH  = sp + O_WOH;  char* pWOL  = sp + O_WOL;
    char* pAH   = sp + O_AH;   char* pAL   = sp + O_AL;
    float* b0s = (float*)(sp + O_B0);
    float* b1s = (float*)(sp + O_B1);
    float* bos = (float*)(sp + O_BO);
    const uint32_t MB = base + O_MB;

    // stacked W01: rows 0-63 = W0r, rows 64-127 = W0l (B layout: (n, k))
    for (int i = tid; i < 128 * 128; i += 256) {
        int k = i >> 7, n = i & 127;
        float v = (k < 64) ? W0r[k * 128 + n] : W0l[(k - 64) * 128 + n];
        __nv_bfloat16 h = __float2bfloat16(v);
        __nv_bfloat16 l = __float2bfloat16(v - __bfloat162float(h));
        uint32_t o = swz_bf16(n, k, 16);
        *(__nv_bfloat16*)(pW01H + o) = h;
        *(__nv_bfloat16*)(pW01L + o) = l;
    }
    for (int i = tid; i < 128 * 128; i += 256) {
        int k = i >> 7, n = i & 127;
        float v = W1r[i];
        __nv_bfloat16 h = __float2bfloat16(v);
        __nv_bfloat16 l = __float2bfloat16(v - __bfloat162float(h));
        uint32_t o = swz_bf16(n, k, 16);
        *(__nv_bfloat16*)(pW1H + o) = h;
        *(__nv_bfloat16*)(pW1L + o) = l;
    }
    for (int i = tid; i < 128 * 32; i += 256) {
        int k = i >> 5, n = i & 31;
        float v = Wo[i];
        __nv_bfloat16 h = __float2bfloat16(v);
        __nv_bfloat16 l = __float2bfloat16(v - __bfloat162float(h));
        uint32_t o = swz_bf16(n, k, 4);
        *(__nv_bfloat16*)(pWOH + o) = h;
        *(__nv_bfloat16*)(pWOL + o) = l;
    }
    for (int i = tid; i < 128; i += 256) { b0s[i] = b0[i]; b1s[i] = b1[i]; }
    if (tid < 32) bos[tid] = bo[tid];
    if (tid == 0) { mbar_init(MB, 1); mbar_init(MB + 8, 1); mbar_init(MB + 16, 1); }
    if (wid == 0) {
        asm volatile("tcgen05.alloc.cta_group::1.sync.aligned.shared::cta.b32 [%0], %1;"
                     :: "r"(base + O_TP), "r"(512) : "memory");
    }
    FENCE_PROXY();
    __syncthreads();
    uint32_t tmem;
    asm volatile("ld.shared.b32 %0, [%1];" : "=r"(tmem) : "r"(base + O_TP));

    const ull dAH = mkdesc(base + O_AH),   dAL = mkdesc(base + O_AL);
    const ull d0H = mkdesc(base + O_W01H), d0L = mkdesc(base + O_W01L);
    const ull d1H = mkdesc(base + O_W1H),  d1L = mkdesc(base + O_W1L);
    const ull dOH = mkdesc(base + O_WOH),  dOL = mkdesc(base + O_WOL);
    const uint32_t idesc128 = 0x8200490u;
    const uint32_t idesc32  = 0x8080490u;

    const int sub = wid & 3, half = wid >> 2;
    const int r = sub * 32 + lane;              // epilogue-owned tile row
    const uint32_t tmoff = (uint32_t)sub << 21;
    const int c0a = half * 32;                  // first 32-col chunk
    const int c0b = 64 + half * 32;             // second chunk

    const int NT = (N_FLOW + 127) / 128;
    int it = 0;
    for (int tile = blockIdx.x; tile < NT; tile += gridDim.x, ++it) {
        const int row0 = tile << 7;
        const int par = it & 1;
        const int ge = row0 + r;
        __syncthreads();                        // prior-tile consumers done

        // per-thread inv for epilogue-2 row
        float invF = 1.f;
        if (ge < N_FLOW) invF = 1.f / fmaxf(__ldg(cnt + ge), 1.f);

        // ---- A tile for phase 1: [x_flow | aggX*inv], 128 rows x 128 cols ----
        {
            int arow = tid >> 1, sel = tid & 1;
            int g = row0 + arow;
            if (g < N_FLOW) {
                if (sel == 0) {
                    const float4* src = (const float4*)(xf + (size_t)g * 64);
#pragma unroll
                    for (int i = 0; i < 16; i++) {
                        float4 v = src[i];
                        store_pair(pAH, pAL, arow, i * 4,     v.x, v.y);
                        store_pair(pAH, pAL, arow, i * 4 + 2, v.z, v.w);
                    }
                } else {
                    float inv = 1.f / fmaxf(__ldg(cnt + g), 1.f);
                    const float4* src = (const float4*)(aggX + (size_t)g * 64);
#pragma unroll
                    for (int i = 0; i < 16; i++) {
                        float4 v = src[i];
                        store_pair(pAH, pAL, arow, 64 + i * 4,     v.x * inv, v.y * inv);
                        store_pair(pAH, pAL, arow, 64 + i * 4 + 2, v.z * inv, v.w * inv);
                    }
                }
            }
        }
        FENCE_PROXY();
        __syncthreads();

        // ---- phase 1 MMA: D = [x|agg] @ W01 (K=128) ----
        const int AO[8] = {0, 2, 4, 6, 1024, 1026, 1028, 1030};
        if (wid == 0 && elect1()) {
#pragma unroll
            for (int s = 0; s < 8; s++) mma_ss_f16(tmem, dAH + AO[s], d0H + AO[s], idesc128, s > 0);
#pragma unroll
            for (int s = 0; s < 8; s++) mma_ss_f16(tmem, dAH + AO[s], d0L + AO[s], idesc128, 1);
#pragma unroll
            for (int s = 0; s < 8; s++) mma_ss_f16(tmem, dAL + AO[s], d0H + AO[s], idesc128, 1);
            tc_commit(MB);
        }
        mbar_wait(MB, par);
        TC_FENCE_A();

        // ---- epilogue 1: H = lrelu(D + b0) -> AH/AL ----
        {
            uint32_t dr[32];
            ldtm32(dr, tmem + c0a + tmoff);
            TC_WAIT_LD();
            if (ge < N_FLOW) {
#pragma unroll
                for (int j = 0; j < 32; j += 2) {
                    float v0 = lrelu(__uint_as_float(dr[j])     + b0s[c0a + j]);
                    float v1 = lrelu(__uint_as_float(dr[j + 1]) + b0s[c0a + j + 1]);
                    store_pair(pAH, pAL, r, c0a + j, v0, v1);
                }
            }
            ldtm32(dr, tmem + c0b + tmoff);
            TC_WAIT_LD();
            if (ge < N_FLOW) {
#pragma unroll
                for (int j = 0; j < 32; j += 2) {
                    float v0 = lrelu(__uint_as_float(dr[j])     + b0s[c0b + j]);
                    float v1 = lrelu(__uint_as_float(dr[j + 1]) + b0s[c0b + j + 1]);
                    store_pair(pAH, pAL, r, c0b + j, v0, v1);
                }
            }
        }
        TC_FENCE_B();
        FENCE_PROXY();
        __syncthreads();

        // ---- phase 2 MMA: D = H @ W1 (K=128) ----
        if (wid == 0 && elect1()) {
#pragma unroll
            for (int s = 0; s < 8; s++) mma_ss_f16(tmem, dAH + AO[s], d1H + AO[s], idesc128, s > 0);
#pragma unroll
            for (int s = 0; s < 8; s++) mma_ss_f16(tmem, dAH + AO[s], d1L + AO[s], idesc128, 1);
#pragma unroll
            for (int s = 0; s < 8; s++) mma_ss_f16(tmem, dAL + AO[s], d1H + AO[s], idesc128, 1);
            tc_commit(MB + 8);
        }
        // prefetch agg2 row-halves (overlaps MMA)
        float4 q0[8], q1[8];
        if (ge < N_FLOW) {
            const float4* ap = (const float4*)(agg2 + (size_t)ge * 128);
#pragma unroll
            for (int i = 0; i < 8; i++) q0[i] = ap[(c0a >> 2) + i];
#pragma unroll
            for (int i = 0; i < 8; i++) q1[i] = ap[(c0b >> 2) + i];
        }
        mbar_wait(MB + 8, par);
        TC_FENCE_A();

        // ---- epilogue 2: g = lrelu(D + agg2*inv + b1) -> AH/AL ----
        {
            uint32_t dr[32];
            ldtm32(dr, tmem + c0a + tmoff);
            TC_WAIT_LD();
            if (ge < N_FLOW) {
#pragma unroll
                for (int j = 0; j < 32; j += 4) {
                    float4 av = q0[j >> 2];
                    float v0 = lrelu(__uint_as_float(dr[j])     + av.x * invF + b1s[c0a + j]);
                    float v1 = lrelu(__uint_as_float(dr[j + 1]) + av.y * invF + b1s[c0a + j + 1]);
                    float v2 = lrelu(__uint_as_float(dr[j + 2]) + av.z * invF + b1s[c0a + j + 2]);
                    float v3 = lrelu(__uint_as_float(dr[j + 3]) + av.w * invF + b1s[c0a + j + 3]);
                    store_pair(pAH, pAL, r, c0a + j,     v0, v1);
                    store_pair(pAH, pAL, r, c0a + j + 2, v2, v3);
                }
            }
            ldtm32(dr, tmem + c0b + tmoff);
            TC_WAIT_LD();
            if (ge < N_FLOW) {
#pragma unroll
                for (int j = 0; j < 32; j += 4) {
                    float4 av = q1[j >> 2];
                    float v0 = lrelu(__uint_as_float(dr[j])     + av.x * invF + b1s[c0b + j]);
                    float v1 = lrelu(__uint_as_float(dr[j + 1]) + av.y * invF + b1s[c0b + j + 1]);
                    float v2 = lrelu(__uint_as_float(dr[j + 2]) + av.z * invF + b1s[c0b + j + 2]);
                    float v3 = lrelu(__uint_as_float(dr[j + 3]) + av.w * invF + b1s[c0b + j + 3]);
                    store_pair(pAH, pAL, r, c0b + j,     v0, v1);
                    store_pair(pAH, pAL, r, c0b + j + 2, v2, v3);
                }
            }
        }
        TC_FENCE_B();
        FENCE_PROXY();
        __syncthreads();

        // ---- phase 3 MMA: D(0..31) = g @ Wout (K=128, N=32) ----
        if (wid == 0 && elect1()) {
            const int BO[8] = {0, 2, 4, 6, 256, 258, 260, 262};
#pragma unroll
            for (int s = 0; s < 8; s++) mma_ss_f16(tmem, dAH + AO[s], dOH + BO[s], idesc32, s > 0);
#pragma unroll
            for (int s = 0; s < 8; s++) mma_ss_f16(tmem, dAH + AO[s], dOL + BO[s], idesc32, 1);
#pragma unroll
            for (int s = 0; s < 8; s++) mma_ss_f16(tmem, dAL + AO[s], dOH + BO[s], idesc32, 1);
            tc_commit(MB + 16);
        }
        mbar_wait(MB + 16, par);
        TC_FENCE_A();

        // ---- epilogue 3: out = D + bout ----
        if (wid < 4) {
            uint32_t dr[32];
            ldtm32(dr, tmem + tmoff);
            TC_WAIT_LD();
            if (ge < N_FLOW) {
                float* op = out + (size_t)ge * 32;
#pragma unroll
                for (int c = 0; c < 32; c += 4) {
                    float4 o = make_float4(__uint_as_float(dr[c])     + bos[c],
                                           __uint_as_float(dr[c + 1]) + bos[c + 1],
                                           __uint_as_float(dr[c + 2]) + bos[c + 2],
                                           __uint_as_float(dr[c + 3]) + bos[c + 3]);
                    *(float4*)(op + c) = o;
                }
            }
        }
        TC_FENCE_B();
    }

    __syncthreads();
    if (wid == 0) {
        asm volatile("tcgen05.relinquish_alloc_permit.cta_group::1.sync.aligned;");
        asm volatile("tcgen05.dealloc.cta_group::1.sync.aligned.b32 %0, %1;" :: "r"(tmem), "r"(512));
    }
#else
    // ==================== FFMA2 fallback path ====================
    // smem: Ws0a(64x128) Ws0b(64x128) Ws1(128x128) Asf(128x68) H(128x129)
    float* Ws0a = (float*)smem_raw;
    float* Ws0b = Ws0a + 64 * 128;
    float* Ws1  = Ws0b + 64 * 128;
    float* Asf  = Ws1 + 128 * 128;
    float* H    = Asf + 128 * 68;

    const int tid = threadIdx.x;
    for (int f = tid; f < 64 * 128 / 4; f += 256) {
        ((float4*)Ws0a)[f] = ((const float4*)W0r)[f];
        ((float4*)Ws0b)[f] = ((const float4*)W0l)[f];
    }
    for (int f = tid; f < 128 * 128 / 4; f += 256) ((float4*)Ws1)[f] = ((const float4*)W1r)[f];

    const int tr8 = (tid >> 4) * 8;
    const int tc8 = (tid & 15) * 8;
    float b0r[8], b1r[8];
#pragma unroll
    for (int j = 0; j < 8; j++) { b0r[j] = b0[tc8 + j]; b1r[j] = b1[tc8 + j]; }
    const int r4 = (tid >> 3) * 4;
    const int c4 = (tid & 7) * 4;
    float bor[4];
#pragma unroll
    for (int j = 0; j < 4; j++) bor[j] = bo[c4 + j];

    const int NT = (N_FLOW + 127) / 128;
    for (int tile = blockIdx.x; tile < NT; tile += gridDim.x) {
        const int row0 = tile * 128;
        __syncthreads();
        // A1 = x tile
        for (int f = tid; f < 2048; f += 256) {
            int r = f >> 4, cc = (f & 15) * 4;
            int gr = row0 + r;
            if (gr < N_FLOW)
                *(float4*)(Asf + r * 68 + cc) = *(const float4*)(xf + (size_t)gr * 64 + cc);
        }
        __syncthreads();

        ull acc[8][4];
        zero_acc(acc);
        mma_tile<64, 68>(Asf, Ws0a, tr8, tc8, acc);
        __syncthreads();
        // A2 = aggX * inv tile
        for (int f = tid; f < 2048; f += 256) {
            int r = f >> 4, cc = (f & 15) * 4;
            int gr = row0 + r;
            if (gr < N_FLOW) {
                float inv = 1.f / fmaxf(__ldg(cnt + gr), 1.f);
                float4 v = *(const float4*)(aggX + (size_t)gr * 64 + cc);
                v.x *= inv; v.y *= inv; v.z *= inv; v.w *= inv;
                *(float4*)(Asf + r * 68 + cc) = v;
            }
        }
        __syncthreads();
        mma_tile<64, 68>(Asf, Ws0b, tr8, tc8, acc);

#pragma unroll
        for (int i = 0; i < 8; i++) {
            int gr = row0 + tr8 + i;
            if (gr >= N_FLOW) continue;
#pragma unroll
            for (int p = 0; p < 4; p++) {
                float2 v = *reinterpret_cast<float2*>(&acc[i][p]);
                H[(tr8 + i) * 129 + tc8 + 2 * p]     = lrelu(v.x + b0r[2 * p]);
                H[(tr8 + i) * 129 + tc8 + 2 * p + 1] = lrelu(v.y + b0r[2 * p + 1]);
            }
        }
        __syncthreads();

        zero_acc(acc);
        mma_tile<128, 129>(H, Ws1, tr8, tc8, acc);
        __syncthreads();
#pragma unroll
        for (int i = 0; i < 8; i++) {
            int gr = row0 + tr8 + i;
            if (gr >= N_FLOW) continue;
            float inv = 1.f / fmaxf(__ldg(cnt + gr), 1.f);
            float4 p0 = *(const float4*)(agg2 + (size_t)gr * 128 + tc8);
            float4 p1 = *(const float4*)(agg2 + (size_t)gr * 128 + tc8 + 4);
            float pv[8] = {p0.x, p0.y, p0.z, p0.w, p1.x, p1.y, p1.z, p1.w};
#pragma unroll
            for (int p = 0; p < 4; p++) {
                float2 v = *reinterpret_cast<float2*>(&acc[i][p]);
                H[(tr8 + i) * 129 + tc8 + 2 * p]     = lrelu(v.x + pv[2 * p] * inv + b1r[2 * p]);
                H[(tr8 + i) * 129 + tc8 + 2 * p + 1] = lrelu(v.y + pv[2 * p + 1] * inv + b1r[2 * p + 1]);
            }
        }
        __syncthreads();

        ull acc3[4][2];
#pragma unroll
        for (int i = 0; i < 4; i++) { acc3[i][0] = 0ull; acc3[i][1] = 0ull; }
#pragma unroll 4
        for (int kk = 0; kk < 128; kk++) {
            float4 wv = __ldg((const float4*)(Wo + kk * 32 + c4));
            ull wx, wy;
            asm("mov.b64 %0, {%1, %2};" : "=l"(wx) : "f"(wv.x), "f"(wv.y));
            asm("mov.b64 %0, {%1, %2};" : "=l"(wy) : "f"(wv.z), "f"(wv.w));
#pragma unroll
            for (int i = 0; i < 4; i++) {
                ull ad = dup2(H[(r4 + i) * 129 + kk]);
                ffma2(acc3[i][0], ad, wx);
                ffma2(acc3[i][1], ad, wy);
            }
        }
#pragma unroll
        for (int i = 0; i < 4; i++) {
            int gr = row0 + r4 + i;
            if (gr >= N_FLOW) continue;
            float2 v0 = *reinterpret_cast<float2*>(&acc3[i][0]);
            float2 v1 = *reinterpret_cast<float2*>(&acc3[i][1]);
            *(float4*)(out + (size_t)gr * 32 + c4) =
                make_float4(v0.x + bor[0], v0.y + bor[1], v1.x + bor[2], v1.y + bor[3]);
        }
    }
#endif
}

// ---------------- host launcher ----------------
extern "C" void kernel_launch(void* const* d_in, const int* in_sizes, int n_in,
                              void* d_out, int out_size)
{
    const float* x_host  = (const float*)d_in[0];
    const float* x_flow  = (const float*)d_in[1];
    const int*   src_hf  = (const int*)d_in[2];
    const int*   dst_hf  = (const int*)d_in[3];
    const int*   src_fh  = (const int*)d_in[4];
    const int*   dst_fh  = (const int*)d_in[5];
    const float* W0_hf_l = (const float*)d_in[6];
    const float* W0_hf_r = (const float*)d_in[7];
    const float* b0_hf   = (const float*)d_in[8];
    const float* W0_fh_l = (const float*)d_in[9];
    const float* W0_fh_r = (const float*)d_in[10];
    const float* b0_fh   = (const float*)d_in[11];
    const float* W1_hf_l = (const float*)d_in[12];
    const float* W1_hf_r = (const float*)d_in[13];
    const float* b1_hf   = (const float*)d_in[14];
    // d_in[15..17] unused (g_host discarded)
    const float* W_out   = (const float*)d_in[18];
    const float* b_out   = (const float*)d_in[19];
    float* out = (float*)d_out;

    float *xr, *aggX, *cntF, *aggH, *cntH, *th1, *agg2;
    cudaGetSymbolAddress((void**)&xr,   g_xr);
    cudaGetSymbolAddress((void**)&aggX, g_aggX);
    cudaGetSymbolAddress((void**)&cntF, g_cntF);
    cudaGetSymbolAddress((void**)&aggH, g_aggH);
    cudaGetSymbolAddress((void**)&cntH, g_cntH);
    cudaGetSymbolAddress((void**)&th1,  g_th1);
    cudaGetSymbolAddress((void**)&agg2, g_agg2);

    cudaFuncSetAttribute(k_xr, cudaFuncAttributeMaxDynamicSharedMemorySize, (int)sizeof(XrSmem));
    cudaFuncSetAttribute(k_host, cudaFuncAttributeMaxDynamicSharedMemorySize, (int)sizeof(HostSmem));
    cudaFuncSetAttribute(k_flow_tc, cudaFuncAttributeMaxDynamicSharedMemorySize, FLOW_SMEM_REQ);

    // 1. zero accumulators
    k_zero<<<2048, 256>>>();

    // 2. aggX[dst_hf] += x_host[src_hf]; cntF++   (64-dim; replaces old 128-dim tx0 scatter)
    k_scatter<<<(NE + 15) / 16, 256>>>(x_host, src_hf, dst_hf, aggX, cntF, NE, D_IN);

    // 3. aggH[dst_fh] += x_flow[src_fh]; cntH++
    k_scatter<<<(NE + 15) / 16, 256>>>(x_flow, src_fh, dst_fh, aggH, cntH, NE, D_IN);

    // 4. xr = x_host @ W0_fh_r
    k_xr<<<157, 256, sizeof(XrSmem)>>>(x_host, W0_fh_r, xr);

    // 5. fused host chain -> th1
    k_host<<<152, 256, sizeof(HostSmem)>>>(aggH, cntH, xr, W0_fh_l, b0_fh, W1_hf_l, th1);

    // 6. agg2[dst_hf] += th1[src_hf]
    k_scatter<<<(NE + 7) / 8, 256>>>(th1, src_hf, dst_hf, agg2, nullptr, NE, D_H);

    // 7. fused flow chain -> out
    k_flow_tc<<<148, 256, FLOW_SMEM_REQ>>>(x_flow, aggX, agg2, cntF,
                                           W0_hf_r, W0_hf_l, b0_hf,
                                           W1_hf_r, b1_hf,
                                           W_out, b_out, out);
}

// round 8
// speedup vs baseline: 1.9688x; 1.0565x over previous
#include <cuda_runtime.h>
#include <cuda_bf16.h>
#include <cstdint>

// Problem constants
#define N_HOST 20000
#define N_FLOW 200000
#define NE     600000
#define D_IN   64
#define D_H    128
#define D_OUT  32

typedef unsigned long long ull;

#if defined(__CUDA_ARCH_FEAT_SM103_ALL) || defined(__CUDA_ARCH_FEAT_SM100_ALL) || defined(__CUDA_ARCH_FEAT_SM101_ALL)
#define HAS_TCGEN05 1
#else
#define HAS_TCGEN05 0
#endif

// ---------------- scratch ----------------
__device__ float g_aggX [(size_t)N_FLOW * D_IN];  // scatter of x_host over hf edges
__device__ float g_cntF [N_FLOW];
__device__ float g_aggH [(size_t)N_HOST * D_IN];  // scatter of x_flow over fh edges
__device__ float g_cntH [N_HOST];
__device__ float g_th1  [(size_t)N_HOST * D_H];   // h_host @ W1_hf_l
__device__ float g_agg2 [(size_t)N_FLOW * D_H];   // scatter of th1 over hf edges

extern __shared__ char smem_raw[];

// ---------------- generic helpers ----------------
__device__ __forceinline__ float lrelu(float v) { return v > 0.f ? v : 0.01f * v; }

__device__ __forceinline__ uint32_t smem_u32(const void* p) {
    uint32_t a;
    asm("{ .reg .u64 t; cvta.to.shared.u64 t, %1; cvt.u32.u64 %0, t; }" : "=r"(a) : "l"(p));
    return a;
}

// ---------------- f32x2 packed-FMA helpers ----------------
__device__ __forceinline__ ull dup2(float x) {
    ull r; asm("mov.b64 %0, {%1, %1};" : "=l"(r) : "f"(x)); return r;
}
__device__ __forceinline__ void ffma2(ull& acc, ull a, ull b) {
    asm("fma.rn.f32x2 %0, %1, %2, %0;" : "+l"(acc) : "l"(a), "l"(b));
}

template <int K, int AP>
__device__ __forceinline__ void mma_tile(const float* __restrict__ As,
                                         const float* __restrict__ Ws,
                                         int tr8, int tc8, ull acc[8][4])
{
#pragma unroll 4
    for (int kk = 0; kk < K; kk++) {
        const ulonglong2* wp = reinterpret_cast<const ulonglong2*>(Ws + kk * 128 + tc8);
        ulonglong2 w01 = wp[0];
        ulonglong2 w23 = wp[1];
        ull ad[8];
#pragma unroll
        for (int i = 0; i < 8; i++) ad[i] = dup2(As[(tr8 + i) * AP + kk]);
#pragma unroll
        for (int i = 0; i < 8; i++) {
            ffma2(acc[i][0], ad[i], w01.x);
            ffma2(acc[i][1], ad[i], w01.y);
            ffma2(acc[i][2], ad[i], w23.x);
            ffma2(acc[i][3], ad[i], w23.y);
        }
    }
}
__device__ __forceinline__ void zero_acc(ull acc[8][4]) {
#pragma unroll
    for (int i = 0; i < 8; i++)
#pragma unroll
        for (int p = 0; p < 4; p++) acc[i][p] = 0ull;
}

// ---------------- tcgen05 helpers ----------------
#if HAS_TCGEN05
__device__ __forceinline__ bool elect1() {
    uint32_t p;
    asm volatile("{\n\t.reg .pred p;\n\telect.sync _|p, 0xFFFFFFFF;\n\tselp.b32 %0,1,0,p;\n\t}" : "=r"(p));
    return p != 0;
}
__device__ __forceinline__ ull mkdesc(uint32_t addr) {
    return 0x4000404000010000ull | ((ull)(addr >> 4) & 0x3FFFull);
}
// TS-mode MMA: A in TMEM, B in SMEM
__device__ __forceinline__ void mma_ts_f16(uint32_t d, uint32_t a, ull bd, uint32_t idesc, uint32_t acc) {
    asm volatile(
        "{\n\t.reg .pred p;\n\tsetp.ne.u32 p, %5, 0;\n\t"
        "tcgen05.mma.cta_group::1.kind::f16 [%0], [%1], %2, %3, {%4,%4,%4,%4}, p;\n\t}"
        :: "r"(d), "r"(a), "l"(bd), "r"(idesc), "r"(0u), "r"(acc) : "memory");
}
__device__ __forceinline__ void tc_commit(uint32_t mbar) {
    asm volatile("tcgen05.commit.cta_group::1.mbarrier::arrive::one.shared::cluster.b64 [%0];"
                 :: "r"(mbar) : "memory");
}
__device__ __forceinline__ void mbar_init(uint32_t a, uint32_t cnt) {
    asm volatile("mbarrier.init.shared.b64 [%0], %1;" :: "r"(a), "r"(cnt) : "memory");
}
__device__ __forceinline__ void mbar_wait(uint32_t a, uint32_t ph) {
    asm volatile(
        "{\n\t.reg .pred P;\n\tLW%=:\n\t"
        "mbarrier.try_wait.parity.acquire.cta.shared::cta.b64 P, [%0], %1;\n\t"
        "@!P bra LW%=;\n\t}"
        :: "r"(a), "r"(ph) : "memory");
}
#define TC_WAIT_LD()   asm volatile("tcgen05.wait::ld.sync.aligned;" ::: "memory")
#define TC_WAIT_ST()   asm volatile("tcgen05.wait::st.sync.aligned;" ::: "memory")
#define TC_FENCE_B()   asm volatile("tcgen05.fence::before_thread_sync;" ::: "memory")
#define TC_FENCE_A()   asm volatile("tcgen05.fence::after_thread_sync;" ::: "memory")
#define FENCE_PROXY()  asm volatile("fence.proxy.async.shared::cta;" ::: "memory")

__device__ __forceinline__ void ldtm32(uint32_t* r, uint32_t a) {
    asm volatile(
        "tcgen05.ld.sync.aligned.32x32b.x32.b32 "
        "{%0,%1,%2,%3,%4,%5,%6,%7,%8,%9,%10,%11,%12,%13,%14,%15,"
        "%16,%17,%18,%19,%20,%21,%22,%23,%24,%25,%26,%27,%28,%29,%30,%31}, [%32];"
        : "=r"(r[0]), "=r"(r[1]), "=r"(r[2]), "=r"(r[3]), "=r"(r[4]), "=r"(r[5]), "=r"(r[6]), "=r"(r[7]),
          "=r"(r[8]), "=r"(r[9]), "=r"(r[10]), "=r"(r[11]), "=r"(r[12]), "=r"(r[13]), "=r"(r[14]), "=r"(r[15]),
          "=r"(r[16]), "=r"(r[17]), "=r"(r[18]), "=r"(r[19]), "=r"(r[20]), "=r"(r[21]), "=r"(r[22]), "=r"(r[23]),
          "=r"(r[24]), "=r"(r[25]), "=r"(r[26]), "=r"(r[27]), "=r"(r[28]), "=r"(r[29]), "=r"(r[30]), "=r"(r[31])
        : "r"(a));
}
__device__ __forceinline__ void sttm_x8(uint32_t a, const uint32_t* r) {
    asm volatile(
        "tcgen05.st.sync.aligned.32x32b.x8.b32 [%0], {%1,%2,%3,%4,%5,%6,%7,%8};"
        :: "r"(a), "r"(r[0]), "r"(r[1]), "r"(r[2]), "r"(r[3]),
           "r"(r[4]), "r"(r[5]), "r"(r[6]), "r"(r[7]) : "memory");
}
__device__ __forceinline__ void sttm_x16(uint32_t a, const uint32_t* r) {
    asm volatile(
        "tcgen05.st.sync.aligned.32x32b.x16.b32 [%0], "
        "{%1,%2,%3,%4,%5,%6,%7,%8,%9,%10,%11,%12,%13,%14,%15,%16};"
        :: "r"(a), "r"(r[0]), "r"(r[1]), "r"(r[2]), "r"(r[3]),
           "r"(r[4]), "r"(r[5]), "r"(r[6]), "r"(r[7]),
           "r"(r[8]), "r"(r[9]), "r"(r[10]), "r"(r[11]),
           "r"(r[12]), "r"(r[13]), "r"(r[14]), "r"(r[15]) : "memory");
}

__device__ __forceinline__ uint32_t swz_bf16(int row, int col, int nar) {
    uint32_t b = (uint32_t)((row >> 3) + (col >> 6) * nar) * 1024u
               + (uint32_t)(row & 7) * 128u + (uint32_t)(col & 63) * 2u;
    return b ^ ((b >> 3) & 0x70u);
}

// split (v0,v1) -> hi bf16x2 (low half = v0) + lo bf16x2
__device__ __forceinline__ void pack_hilo(float v0, float v1, uint32_t& h, uint32_t& l) {
    asm("cvt.rn.bf16x2.f32 %0, %1, %2;" : "=r"(h) : "f"(v1), "f"(v0));
    float h0 = __uint_as_float(h << 16);
    float h1 = __uint_as_float(h & 0xffff0000u);
    asm("cvt.rn.bf16x2.f32 %0, %1, %2;" : "=r"(l) : "f"(v1 - h1), "f"(v0 - h0));
}
#endif  // HAS_TCGEN05

// ---------------- zero scratch ----------------
__global__ void k_zero() {
    size_t i = (size_t)blockIdx.x * blockDim.x + threadIdx.x;
    size_t stride = (size_t)gridDim.x * blockDim.x;
    const float4 z = make_float4(0.f, 0.f, 0.f, 0.f);
    for (size_t k = i; k < ((size_t)N_FLOW * D_IN) / 4; k += stride) ((float4*)g_aggX)[k] = z;
    for (size_t k = i; k < ((size_t)N_FLOW * D_H) / 4; k += stride) ((float4*)g_agg2)[k] = z;
    for (size_t k = i; k < ((size_t)N_HOST * D_IN) / 4; k += stride) ((float4*)g_aggH)[k] = z;
    for (size_t k = i; k < (size_t)N_FLOW / 4; k += stride) ((float4*)g_cntF)[k] = z;
    for (size_t k = i; k < (size_t)N_HOST / 4; k += stride) ((float4*)g_cntH)[k] = z;
}

// ---------------- combined 64-dim scatters (both directions in one launch) ----------------
__global__ __launch_bounds__(256) void k_scatter64x2(
    const float* __restrict__ xh, const int* __restrict__ src_hf,
    const int* __restrict__ dst_hf, float* __restrict__ aggX, float* __restrict__ cntF,
    const float* __restrict__ xfl, const int* __restrict__ src_fh,
    const int* __restrict__ dst_fh, float* __restrict__ aggH, float* __restrict__ cntH)
{
    int eloc = threadIdx.x >> 4;          // 16 lanes/edge (D=64)
    int lane = threadIdx.x & 15;
    int e2 = blockIdx.x * 16 + eloc;
    const float* feat; const int* srcp; const int* dstp; float* agg; float* cnt;
    int e;
    if (e2 < NE) {
        e = e2; feat = xh; srcp = src_hf; dstp = dst_hf; agg = aggX; cnt = cntF;
    } else {
        e = e2 - NE;
        if (e >= NE) return;
        feat = xfl; srcp = src_fh; dstp = dst_fh; agg = aggH; cnt = cntH;
    }
    int s = __ldg(srcp + e);
    int d = __ldg(dstp + e);
    float4 v = *(const float4*)(feat + (size_t)s * 64 + lane * 4);
    float* p = agg + (size_t)d * 64 + lane * 4;
    asm volatile("red.global.add.v4.f32 [%0], {%1,%2,%3,%4};"
                 :: "l"(p), "f"(v.x), "f"(v.y), "f"(v.z), "f"(v.w) : "memory");
    if (lane == 0) atomicAdd(cnt + d, 1.0f);
}

// ---------------- 128-dim scatter (th1 -> agg2) ----------------
__global__ __launch_bounds__(256) void k_scatter128(
    const float* __restrict__ feat, const int* __restrict__ src,
    const int* __restrict__ dst, float* __restrict__ agg, int E)
{
    int eloc = threadIdx.x >> 5;          // 32 lanes/edge
    int lane = threadIdx.x & 31;
    int e = blockIdx.x * 8 + eloc;
    if (e >= E) return;
    int s = __ldg(src + e);
    int d = __ldg(dst + e);
    float4 v = *(const float4*)(feat + (size_t)s * 128 + lane * 4);
    float* p = agg + (size_t)d * 128 + lane * 4;
    asm volatile("red.global.add.v4.f32 [%0], {%1,%2,%3,%4};"
                 :: "l"(p), "f"(v.x), "f"(v.y), "f"(v.z), "f"(v.w) : "memory");
}

// ---------------- fused host chain (FFMA2, stacked K=128) ----------------
// th1 = ( lrelu([aggH*inv | x_host] @ [W0l; W0r] + b0) ) @ W1l
struct HostSmem {
    float Ws0[128 * 128];
    float Ws1[128 * 128];
    float Buf[128 * 132];    // A tile, then (aliased) H tile
};

__global__ __launch_bounds__(256, 1) void k_host(
    const float* __restrict__ aggH, const float* __restrict__ cntH,
    const float* __restrict__ xh,
    const float* __restrict__ W0l, const float* __restrict__ W0r,
    const float* __restrict__ b0,
    const float* __restrict__ W1l,
    float* __restrict__ th1)
{
    HostSmem* S = reinterpret_cast<HostSmem*>(smem_raw);
    const int tid = threadIdx.x;
    // Ws0: rows 0-63 = W0l, rows 64-127 = W0r
    for (int i = tid; i < 128 * 128; i += 256) {
        int k = i >> 7, n = i & 127;
        S->Ws0[i] = (k < 64) ? W0l[k * 128 + n] : W0r[(k - 64) * 128 + n];
    }
    for (int f = tid; f < 128 * 128 / 4; f += 256) ((float4*)S->Ws1)[f] = ((const float4*)W1l)[f];

    const int tr8 = (tid >> 4) * 8;
    const int tc8 = (tid & 15) * 8;
    float b0r[8];
#pragma unroll
    for (int j = 0; j < 8; j++) b0r[j] = b0[tc8 + j];

    const int NT = (N_HOST + 127) / 128;
    for (int tile = blockIdx.x; tile < NT; tile += gridDim.x) {
        const int row0 = tile * 128;
        __syncthreads();
        // A tile: cols 0-63 = aggH*inv, cols 64-127 = x_host
        for (int f = tid; f < 4096; f += 256) {
            int r = f >> 5, cc = (f & 31) * 4;
            int gr = row0 + r;
            if (gr >= N_HOST) continue;
            float4 v;
            if (cc < 64) {
                float inv = 1.f / fmaxf(__ldg(cntH + gr), 1.f);
                v = *(const float4*)(aggH + (size_t)gr * 64 + cc);
                v.x *= inv; v.y *= inv; v.z *= inv; v.w *= inv;
            } else {
                v = *(const float4*)(xh + (size_t)gr * 64 + (cc - 64));
            }
            *(float4*)(&S->Buf[r * 132 + cc]) = v;
        }
        __syncthreads();

        ull acc[8][4];
        zero_acc(acc);
        mma_tile<128, 132>(S->Buf, S->Ws0, tr8, tc8, acc);
        __syncthreads();     // all A reads done before H overwrites Buf
#pragma unroll
        for (int i = 0; i < 8; i++) {
#pragma unroll
            for (int p = 0; p < 4; p++) {
                float2 v = *reinterpret_cast<float2*>(&acc[i][p]);
                S->Buf[(tr8 + i) * 132 + tc8 + 2 * p]     = lrelu(v.x + b0r[2 * p]);
                S->Buf[(tr8 + i) * 132 + tc8 + 2 * p + 1] = lrelu(v.y + b0r[2 * p + 1]);
            }
        }
        __syncthreads();

        zero_acc(acc);
        mma_tile<128, 132>(S->Buf, S->Ws1, tr8, tc8, acc);
#pragma unroll
        for (int i = 0; i < 8; i++) {
            int gr = row0 + tr8 + i;
            if (gr >= N_HOST) continue;
            float2 v0 = *reinterpret_cast<float2*>(&acc[i][0]);
            float2 v1 = *reinterpret_cast<float2*>(&acc[i][1]);
            float2 v2 = *reinterpret_cast<float2*>(&acc[i][2]);
            float2 v3 = *reinterpret_cast<float2*>(&acc[i][3]);
            *(float4*)(th1 + (size_t)gr * 128 + tc8)     = make_float4(v0.x, v0.y, v1.x, v1.y);
            *(float4*)(th1 + (size_t)gr * 128 + tc8 + 4) = make_float4(v2.x, v2.y, v3.x, v3.y);
        }
    }
}

// ================= flow chain =================
// tcgen05 smem layout (bytes from 1024-aligned base): weights + biases only
#define O_W01H 0
#define O_W01L 32768
#define O_W1H  65536
#define O_W1L  98304
#define O_WOH  131072
#define O_WOL  139264
#define O_B0   147456
#define O_B1   147968
#define O_BO   148480
#define O_MB   148608
#define O_TP   148640
// TMEM column map: A parity0 [0,128), A parity1 [128,256), D [256,384)
#define TM_PA0 0
#define TM_PA1 128
#define TM_D   256

#define FLOW_SMEM_REQ 231936   // covers FFMA2 fallback too

__global__ __launch_bounds__(256, 1)
void k_flow_tc(const float* __restrict__ xf,
               const float* __restrict__ aggX, const float* __restrict__ agg2,
               const float* __restrict__ cnt,
               const float* __restrict__ W0r, const float* __restrict__ W0l,
               const float* __restrict__ b0,
               const float* __restrict__ W1r, const float* __restrict__ b1,
               const float* __restrict__ Wo,  const float* __restrict__ bo,
               float* __restrict__ out)
{
#if HAS_TCGEN05
    const int tid = threadIdx.x;
    const int wid = tid >> 5;
    const int lane = tid & 31;

    uint32_t raw = smem_u32(smem_raw);
    uint32_t base = (raw + 1023u) & ~1023u;
    char* sp = smem_raw + (base - raw);

    char* pW01H = sp + O_W01H; char* pW01L = sp + O_W01L;
    char* pW1H  = sp + O_W1H;  char* pW1L  = sp + O_W1L;
    char* pWOH  = sp + O_WOH;  char* pWOL  = sp + O_WOL;
    float* b0s = (float*)(sp + O_B0);
    float* b1s = (float*)(sp + O_B1);
    float* bos = (float*)(sp + O_BO);
    const uint32_t MB = base + O_MB;

    // ---- one-time weight prep (transpose + bf16 split into SW128 tiles) ----
    for (int i = tid; i < 128 * 128; i += 256) {     // stacked [W0r; W0l] -> B(n,k)
        int k = i >> 7, n = i & 127;
        float v = (k < 64) ? W0r[k * 128 + n] : W0l[(k - 64) * 128 + n];
        __nv_bfloat16 h = __float2bfloat16(v);
        __nv_bfloat16 l = __float2bfloat16(v - __bfloat162float(h));
        uint32_t o = swz_bf16(n, k, 16);
        *(__nv_bfloat16*)(pW01H + o) = h;
        *(__nv_bfloat16*)(pW01L + o) = l;
    }
    for (int i = tid; i < 128 * 128; i += 256) {     // W1r -> B(n,k)
        int k = i >> 7, n = i & 127;
        float v = W1r[i];
        __nv_bfloat16 h = __float2bfloat16(v);
        __nv_bfloat16 l = __float2bfloat16(v - __bfloat162float(h));
        uint32_t o = swz_bf16(n, k, 16);
        *(__nv_bfloat16*)(pW1H + o) = h;
        *(__nv_bfloat16*)(pW1L + o) = l;
    }
    for (int i = tid; i < 128 * 32; i += 256) {      // Wo -> B(n,k), n<32
        int k = i >> 5, n = i & 31;
        float v = Wo[i];
        __nv_bfloat16 h = __float2bfloat16(v);
        __nv_bfloat16 l = __float2bfloat16(v - __bfloat162float(h));
        uint32_t o = swz_bf16(n, k, 4);
        *(__nv_bfloat16*)(pWOH + o) = h;
        *(__nv_bfloat16*)(pWOL + o) = l;
    }
    for (int i = tid; i < 128; i += 256) { b0s[i] = b0[i]; b1s[i] = b1[i]; }
    if (tid < 32) bos[tid] = bo[tid];
    if (tid == 0) { mbar_init(MB, 1); mbar_init(MB + 8, 1); mbar_init(MB + 16, 1); }
    if (wid == 0) {
        asm volatile("tcgen05.alloc.cta_group::1.sync.aligned.shared::cta.b32 [%0], %1;"
                     :: "r"(base + O_TP), "r"(512) : "memory");
    }
    FENCE_PROXY();
    __syncthreads();
    uint32_t tmem;
    asm volatile("ld.shared.b32 %0, [%1];" : "=r"(tmem) : "r"(base + O_TP));

    const ull d0H = mkdesc(base + O_W01H), d0L = mkdesc(base + O_W01L);
    const ull d1H = mkdesc(base + O_W1H),  d1L = mkdesc(base + O_W1L);
    const ull dOH = mkdesc(base + O_WOH),  dOL = mkdesc(base + O_WOL);
    const uint32_t idesc128 = 0x8200490u;   // M=128 N=128 bf16->f32
    const uint32_t idesc32  = 0x8080490u;   // M=128 N=32

    const int sub = wid & 3, half = wid >> 2;
    const int r = sub * 32 + lane;                  // tile-local row this thread owns
    const uint32_t tm_row = (uint32_t)sub << 21;    // subpartition offset for LDTM/STTM
    const int c0a = half * 32;                      // element-col chunks this warp owns
    const int c0b = 64 + half * 32;
    const uint32_t dT = tmem + TM_D;

    const int NT = (N_FLOW + 127) >> 7;

    // ---- warp-collective A loader: [x | aggX*inv] -> TMEM parity region ----
    // returns inv(cnt) of this thread's row in that tile
    auto load_A = [&](int row0n, uint32_t pa) -> float {
        int gn = row0n + r;
        int gs = gn < N_FLOW ? gn : N_FLOW - 1;
        float inv = 1.f / fmaxf(__ldg(cnt + gs), 1.f);
        const float* src = half ? (aggX + (size_t)gs * 64) : (xf + (size_t)gs * 64);
        float sc = half ? inv : 1.f;
        uint32_t A0 = tmem + pa + (uint32_t)(half * 32) + tm_row;
#pragma unroll
        for (int q = 0; q < 4; q++) {
            const float4* p4 = (const float4*)(src + q * 16);
            float4 f0 = p4[0], f1 = p4[1], f2 = p4[2], f3 = p4[3];
            float e[16] = {f0.x, f0.y, f0.z, f0.w, f1.x, f1.y, f1.z, f1.w,
                           f2.x, f2.y, f2.z, f2.w, f3.x, f3.y, f3.z, f3.w};
            uint32_t hi[8], lo[8];
#pragma unroll
            for (int i = 0; i < 8; i++) pack_hilo(e[2 * i] * sc, e[2 * i + 1] * sc, hi[i], lo[i]);
            sttm_x8(A0 + q * 8, hi);
            sttm_x8(A0 + 64 + q * 8, lo);
        }
        TC_WAIT_ST();
        return inv;
    };

    // MMA phase helper: 3 bf16-split passes, K=128
    const int BO128_0 = 0;  // W1/W01 desc steps: {0,2,4,6,1024,1026,1028,1030}
    auto mma_phase = [&](uint32_t a0, ull bh, ull bl, const int* BO, uint32_t idesc) {
#pragma unroll
        for (int s = 0; s < 8; s++) mma_ts_f16(dT, a0 + s * 8, bh + BO[s], idesc, s > 0);
#pragma unroll
        for (int s = 0; s < 8; s++) mma_ts_f16(dT, a0 + s * 8, bl + BO[s], idesc, 1);
#pragma unroll
        for (int s = 0; s < 8; s++) mma_ts_f16(dT, a0 + 64 + s * 8, bh + BO[s], idesc, 1);
    };
    const int BOW[8] = {0, 2, 4, 6, 1024, 1026, 1028, 1030};
    const int BOO[8] = {0, 2, 4, 6, 256, 258, 260, 262};
    (void)BO128_0;

    // ---- prologue: load A for first tile into parity 0 ----
    float invC = 1.f;
    if (blockIdx.x < NT) invC = load_A(blockIdx.x << 7, TM_PA0);
    TC_FENCE_B();

    int it = 0;
    for (int tile = blockIdx.x; tile < NT; tile += gridDim.x, ++it) {
        const int cur = it & 1;
        const int par = it & 1;
        const uint32_t PAc = tmem + (cur ? TM_PA1 : TM_PA0);
        const uint32_t PAn = tmem + (cur ? TM_PA0 : TM_PA1);
        const int row0 = tile << 7;
        const int ge = row0 + r;
        __syncthreads();                            // prior-iter epi3 + A STTMs done

        // ---- phase 1 MMA: D = [x|agg] @ W01 ----
        if (wid == 0) {
            TC_FENCE_A();
            if (elect1()) { mma_phase(PAc, d0H, d0L, BOW, idesc128); tc_commit(MB); }
        }
        // ---- overlap: load next tile's A into the other parity ----
        float invN = 1.f;
        int tnext = tile + gridDim.x;
        if (tnext < NT) { invN = load_A(tnext << 7, PAn); TC_FENCE_B(); }

        mbar_wait(MB, par);
        TC_FENCE_A();

        // ---- epilogue 1: H = lrelu(D + b0) -> TMEM A(cur) ----
        {
            uint32_t dr[32], hi[16], lo[16];
            ldtm32(dr, dT + c0a + tm_row);
            TC_WAIT_LD();
#pragma unroll
            for (int j = 0; j < 32; j += 2) {
                float v0 = lrelu(__uint_as_float(dr[j])     + b0s[c0a + j]);
                float v1 = lrelu(__uint_as_float(dr[j + 1]) + b0s[c0a + j + 1]);
                pack_hilo(v0, v1, hi[j >> 1], lo[j >> 1]);
            }
            sttm_x16(PAc + (c0a >> 1) + tm_row, hi);
            sttm_x16(PAc + 64 + (c0a >> 1) + tm_row, lo);
            ldtm32(dr, dT + c0b + tm_row);
            TC_WAIT_LD();
#pragma unroll
            for (int j = 0; j < 32; j += 2) {
                float v0 = lrelu(__uint_as_float(dr[j])     + b0s[c0b + j]);
                float v1 = lrelu(__uint_as_float(dr[j + 1]) + b0s[c0b + j + 1]);
                pack_hilo(v0, v1, hi[j >> 1], lo[j >> 1]);
            }
            sttm_x16(PAc + (c0b >> 1) + tm_row, hi);
            sttm_x16(PAc + 64 + (c0b >> 1) + tm_row, lo);
            TC_WAIT_ST();
        }
        TC_FENCE_B();
        __syncthreads();

        // ---- phase 2 MMA: D = H @ W1 ----
        if (wid == 0) {
            TC_FENCE_A();
            if (elect1()) { mma_phase(PAc, d1H, d1L, BOW, idesc128); tc_commit(MB + 8); }
        }
        // prefetch agg2 row (overlaps MMA2)
        float4 q0[8], q1[8];
        {
            int gs = ge < N_FLOW ? ge : N_FLOW - 1;
            const float4* ap = (const float4*)(agg2 + (size_t)gs * 128);
#pragma unroll
            for (int i = 0; i < 8; i++) q0[i] = ap[(c0a >> 2) + i];
#pragma unroll
            for (int i = 0; i < 8; i++) q1[i] = ap[(c0b >> 2) + i];
        }
        mbar_wait(MB + 8, par);
        TC_FENCE_A();

        // ---- epilogue 2: g = lrelu(D + agg2*inv + b1) -> TMEM A(cur) ----
        {
            uint32_t dr[32], hi[16], lo[16];
            ldtm32(dr, dT + c0a + tm_row);
            TC_WAIT_LD();
#pragma unroll
            for (int j = 0; j < 32; j += 2) {
                float a0v = (j & 2) ? ((j & 1) ? 0.f : q0[j >> 2].z) : q0[j >> 2].x;
                // unrolled float4 lane picks below instead
                (void)a0v;
                break;
            }
#pragma unroll
            for (int j = 0; j < 32; j += 4) {
                float4 av = q0[j >> 2];
                float v0 = lrelu(__uint_as_float(dr[j])     + av.x * invC + b1s[c0a + j]);
                float v1 = lrelu(__uint_as_float(dr[j + 1]) + av.y * invC + b1s[c0a + j + 1]);
                float v2 = lrelu(__uint_as_float(dr[j + 2]) + av.z * invC + b1s[c0a + j + 2]);
                float v3 = lrelu(__uint_as_float(dr[j + 3]) + av.w * invC + b1s[c0a + j + 3]);
                pack_hilo(v0, v1, hi[j >> 1], lo[j >> 1]);
                pack_hilo(v2, v3, hi[(j >> 1) + 1], lo[(j >> 1) + 1]);
            }
            sttm_x16(PAc + (c0a >> 1) + tm_row, hi);
            sttm_x16(PAc + 64 + (c0a >> 1) + tm_row, lo);
            ldtm32(dr, dT + c0b + tm_row);
            TC_WAIT_LD();
#pragma unroll
            for (int j = 0; j < 32; j += 4) {
                float4 av = q1[j >> 2];
                float v0 = lrelu(__uint_as_float(dr[j])     + av.x * invC + b1s[c0b + j]);
                float v1 = lrelu(__uint_as_float(dr[j + 1]) + av.y * invC + b1s[c0b + j + 1]);
                float v2 = lrelu(__uint_as_float(dr[j + 2]) + av.z * invC + b1s[c0b + j + 2]);
                float v3 = lrelu(__uint_as_float(dr[j + 3]) + av.w * invC + b1s[c0b + j + 3]);
                pack_hilo(v0, v1, hi[j >> 1], lo[j >> 1]);
                pack_hilo(v2, v3, hi[(j >> 1) + 1], lo[(j >> 1) + 1]);
            }
            sttm_x16(PAc + (c0b >> 1) + tm_row, hi);
            sttm_x16(PAc + 64 + (c0b >> 1) + tm_row, lo);
            TC_WAIT_ST();
        }
        TC_FENCE_B();
        __syncthreads();

        // ---- phase 3 MMA: D(0..31) = g @ Wout ----
        if (wid == 0) {
            TC_FENCE_A();
            if (elect1()) { mma_phase(PAc, dOH, dOL, BOO, idesc32); tc_commit(MB + 16); }
        }
        mbar_wait(MB + 16, par);
        TC_FENCE_A();

        // ---- epilogue 3: out = D + bout ----
        if (wid < 4) {
            uint32_t dr[32];
            ldtm32(dr, dT + tm_row);
            TC_WAIT_LD();
            if (ge < N_FLOW) {
                float* op = out + (size_t)ge * 32;
#pragma unroll
                for (int c = 0; c < 32; c += 4) {
                    *(float4*)(op + c) = make_float4(
                        __uint_as_float(dr[c])     + bos[c],
                        __uint_as_float(dr[c + 1]) + bos[c + 1],
                        __uint_as_float(dr[c + 2]) + bos[c + 2],
                        __uint_as_float(dr[c + 3]) + bos[c + 3]);
                }
            }
        }
        TC_FENCE_B();
        invC = invN;
    }

    __syncthreads();
    if (wid == 0) {
        asm volatile("tcgen05.relinquish_alloc_permit.cta_group::1.sync.aligned;");
        asm volatile("tcgen05.dealloc.cta_group::1.sync.aligned.b32 %0, %1;" :: "r"(tmem), "r"(512));
    }
#else
    // ==================== FFMA2 fallback path ====================
    float* Ws0a = (float*)smem_raw;
    float* Ws0b = Ws0a + 64 * 128;
    float* Ws1  = Ws0b + 64 * 128;
    float* Asf  = Ws1 + 128 * 128;
    float* H    = Asf + 128 * 68;

    const int tid = threadIdx.x;
    for (int f = tid; f < 64 * 128 / 4; f += 256) {
        ((float4*)Ws0a)[f] = ((const float4*)W0r)[f];
        ((float4*)Ws0b)[f] = ((const float4*)W0l)[f];
    }
    for (int f = tid; f < 128 * 128 / 4; f += 256) ((float4*)Ws1)[f] = ((const float4*)W1r)[f];

    const int tr8 = (tid >> 4) * 8;
    const int tc8 = (tid & 15) * 8;
    float b0r[8], b1r[8];
#pragma unroll
    for (int j = 0; j < 8; j++) { b0r[j] = b0[tc8 + j]; b1r[j] = b1[tc8 + j]; }
    const int r4 = (tid >> 3) * 4;
    const int c4 = (tid & 7) * 4;
    float bor[4];
#pragma unroll
    for (int j = 0; j < 4; j++) bor[j] = bo[c4 + j];

    const int NT = (N_FLOW + 127) / 128;
    for (int tile = blockIdx.x; tile < NT; tile += gridDim.x) {
        const int row0 = tile * 128;
        __syncthreads();
        for (int f = tid; f < 2048; f += 256) {
            int r = f >> 4, cc = (f & 15) * 4;
            int gr = row0 + r;
            if (gr < N_FLOW)
                *(float4*)(Asf + r * 68 + cc) = *(const float4*)(xf + (size_t)gr * 64 + cc);
        }
        __syncthreads();

        ull acc[8][4];
        zero_acc(acc);
        mma_tile<64, 68>(Asf, Ws0a, tr8, tc8, acc);
        __syncthreads();
        for (int f = tid; f < 2048; f += 256) {
            int r = f >> 4, cc = (f & 15) * 4;
            int gr = row0 + r;
            if (gr < N_FLOW) {
                float inv = 1.f / fmaxf(__ldg(cnt + gr), 1.f);
                float4 v = *(const float4*)(aggX + (size_t)gr * 64 + cc);
                v.x *= inv; v.y *= inv; v.z *= inv; v.w *= inv;
                *(float4*)(Asf + r * 68 + cc) = v;
            }
        }
        __syncthreads();
        mma_tile<64, 68>(Asf, Ws0b, tr8, tc8, acc);

#pragma unroll
        for (int i = 0; i < 8; i++) {
            int gr = row0 + tr8 + i;
            if (gr >= N_FLOW) continue;
#pragma unroll
            for (int p = 0; p < 4; p++) {
                float2 v = *reinterpret_cast<float2*>(&acc[i][p]);
                H[(tr8 + i) * 129 + tc8 + 2 * p]     = lrelu(v.x + b0r[2 * p]);
                H[(tr8 + i) * 129 + tc8 + 2 * p + 1] = lrelu(v.y + b0r[2 * p + 1]);
            }
        }
        __syncthreads();

        zero_acc(acc);
        mma_tile<128, 129>(H, Ws1, tr8, tc8, acc);
        __syncthreads();
#pragma unroll
        for (int i = 0; i < 8; i++) {
            int gr = row0 + tr8 + i;
            if (gr >= N_FLOW) continue;
            float inv = 1.f / fmaxf(__ldg(cnt + gr), 1.f);
            float4 p0 = *(const float4*)(agg2 + (size_t)gr * 128 + tc8);
            float4 p1 = *(const float4*)(agg2 + (size_t)gr * 128 + tc8 + 4);
            float pv[8] = {p0.x, p0.y, p0.z, p0.w, p1.x, p1.y, p1.z, p1.w};
#pragma unroll
            for (int p = 0; p < 4; p++) {
                float2 v = *reinterpret_cast<float2*>(&acc[i][p]);
                H[(tr8 + i) * 129 + tc8 + 2 * p]     = lrelu(v.x + pv[2 * p] * inv + b1r[2 * p]);
                H[(tr8 + i) * 129 + tc8 + 2 * p + 1] = lrelu(v.y + pv[2 * p + 1] * inv + b1r[2 * p + 1]);
            }
        }
        __syncthreads();

        ull acc3[4][2];
#pragma unroll
        for (int i = 0; i < 4; i++) { acc3[i][0] = 0ull; acc3[i][1] = 0ull; }
#pragma unroll 4
        for (int kk = 0; kk < 128; kk++) {
            float4 wv = __ldg((const float4*)(Wo + kk * 32 + c4));
            ull wx, wy;
            asm("mov.b64 %0, {%1, %2};" : "=l"(wx) : "f"(wv.x), "f"(wv.y));
            asm("mov.b64 %0, {%1, %2};" : "=l"(wy) : "f"(wv.z), "f"(wv.w));
#pragma unroll
            for (int i = 0; i < 4; i++) {
                ull ad = dup2(H[(r4 + i) * 129 + kk]);
                ffma2(acc3[i][0], ad, wx);
                ffma2(acc3[i][1], ad, wy);
            }
        }
#pragma unroll
        for (int i = 0; i < 4; i++) {
            int gr = row0 + r4 + i;
            if (gr >= N_FLOW) continue;
            float2 v0 = *reinterpret_cast<float2*>(&acc3[i][0]);
            float2 v1 = *reinterpret_cast<float2*>(&acc3[i][1]);
            *(float4*)(out + (size_t)gr * 32 + c4) =
                make_float4(v0.x + bor[0], v0.y + bor[1], v1.x + bor[2], v1.y + bor[3]);
        }
    }
#endif
}

// ---------------- host launcher ----------------
extern "C" void kernel_launch(void* const* d_in, const int* in_sizes, int n_in,
                              void* d_out, int out_size)
{
    const float* x_host  = (const float*)d_in[0];
    const float* x_flow  = (const float*)d_in[1];
    const int*   src_hf  = (const int*)d_in[2];
    const int*   dst_hf  = (const int*)d_in[3];
    const int*   src_fh  = (const int*)d_in[4];
    const int*   dst_fh  = (const int*)d_in[5];
    const float* W0_hf_l = (const float*)d_in[6];
    const float* W0_hf_r = (const float*)d_in[7];
    const float* b0_hf   = (const float*)d_in[8];
    const float* W0_fh_l = (const float*)d_in[9];
    const float* W0_fh_r = (const float*)d_in[10];
    const float* b0_fh   = (const float*)d_in[11];
    const float* W1_hf_l = (const float*)d_in[12];
    const float* W1_hf_r = (const float*)d_in[13];
    const float* b1_hf   = (const float*)d_in[14];
    // d_in[15..17] unused (g_host discarded)
    const float* W_out   = (const float*)d_in[18];
    const float* b_out   = (const float*)d_in[19];
    float* out = (float*)d_out;

    float *aggX, *cntF, *aggH, *cntH, *th1, *agg2;
    cudaGetSymbolAddress((void**)&aggX, g_aggX);
    cudaGetSymbolAddress((void**)&cntF, g_cntF);
    cudaGetSymbolAddress((void**)&aggH, g_aggH);
    cudaGetSymbolAddress((void**)&cntH, g_cntH);
    cudaGetSymbolAddress((void**)&th1,  g_th1);
    cudaGetSymbolAddress((void**)&agg2, g_agg2);

    cudaFuncSetAttribute(k_host, cudaFuncAttributeMaxDynamicSharedMemorySize, (int)sizeof(HostSmem));
    cudaFuncSetAttribute(k_flow_tc, cudaFuncAttributeMaxDynamicSharedMemorySize, FLOW_SMEM_REQ);

    // 1. zero accumulators
    k_zero<<<2048, 256>>>();

    // 2. both 64-dim scatters in one launch
    k_scatter64x2<<<(2 * NE + 15) / 16, 256>>>(x_host, src_hf, dst_hf, aggX, cntF,
                                               x_flow, src_fh, dst_fh, aggH, cntH);

    // 3. fused host chain (stacked K=128) -> th1
    k_host<<<157, 256, sizeof(HostSmem)>>>(aggH, cntH, x_host,
                                           W0_fh_l, W0_fh_r, b0_fh, W1_hf_l, th1);

    // 4. agg2[dst_hf] += th1[src_hf]
    k_scatter128<<<(NE + 7) / 8, 256>>>(th1, src_hf, dst_hf, agg2, NE);

    // 5. fused flow chain -> out
    k_flow_tc<<<148, 256, FLOW_SMEM_REQ>>>(x_flow, aggX, agg2, cntF,
                                           W0_hf_r, W0_hf_l, b0_hf,
                                           W1_hf_r, b1_hf,
                                           W_out, b_out, out);
}

// round 10
// speedup vs baseline: 2.2080x; 1.1215x over previous
#include <cuda_runtime.h>
#include <cuda_bf16.h>
#include <cstdint>

// Problem constants
#define N_HOST 20000
#define N_FLOW 200000
#define NE     600000
#define D_IN   64
#define D_H    128
#define D_OUT  32

typedef unsigned long long ull;

#if defined(__CUDA_ARCH_FEAT_SM103_ALL) || defined(__CUDA_ARCH_FEAT_SM100_ALL) || defined(__CUDA_ARCH_FEAT_SM101_ALL)
#define HAS_TCGEN05 1
#else
#define HAS_TCGEN05 0
#endif

// ---------------- scratch ----------------
__device__ float g_aggX [(size_t)N_FLOW * D_IN];
__device__ float g_cntF [N_FLOW];
__device__ float g_aggH [(size_t)N_HOST * D_IN];
__device__ float g_cntH [N_HOST];
__device__ float g_th1  [(size_t)N_HOST * D_H];
__device__ float g_agg2 [(size_t)N_FLOW * D_H];

extern __shared__ char smem_raw[];

// ---------------- generic helpers ----------------
__device__ __forceinline__ float lrelu(float v) { return v > 0.f ? v : 0.01f * v; }

__device__ __forceinline__ uint32_t smem_u32(const void* p) {
    uint32_t a;
    asm("{ .reg .u64 t; cvta.to.shared.u64 t, %1; cvt.u32.u64 %0, t; }" : "=r"(a) : "l"(p));
    return a;
}

// ---------------- f32x2 packed-FMA helpers ----------------
__device__ __forceinline__ ull dup2(float x) {
    ull r; asm("mov.b64 %0, {%1, %1};" : "=l"(r) : "f"(x)); return r;
}
__device__ __forceinline__ void ffma2(ull& acc, ull a, ull b) {
    asm("fma.rn.f32x2 %0, %1, %2, %0;" : "+l"(acc) : "l"(a), "l"(b));
}

template <int K, int AP>
__device__ __forceinline__ void mma_tile(const float* __restrict__ As,
                                         const float* __restrict__ Ws,
                                         int tr8, int tc8, ull acc[8][4])
{
#pragma unroll 4
    for (int kk = 0; kk < K; kk++) {
        const ulonglong2* wp = reinterpret_cast<const ulonglong2*>(Ws + kk * 128 + tc8);
        ulonglong2 w01 = wp[0];
        ulonglong2 w23 = wp[1];
        ull ad[8];
#pragma unroll
        for (int i = 0; i < 8; i++) ad[i] = dup2(As[(tr8 + i) * AP + kk]);
#pragma unroll
        for (int i = 0; i < 8; i++) {
            ffma2(acc[i][0], ad[i], w01.x);
            ffma2(acc[i][1], ad[i], w01.y);
            ffma2(acc[i][2], ad[i], w23.x);
            ffma2(acc[i][3], ad[i], w23.y);
        }
    }
}
__device__ __forceinline__ void zero_acc(ull acc[8][4]) {
#pragma unroll
    for (int i = 0; i < 8; i++)
#pragma unroll
        for (int p = 0; p < 4; p++) acc[i][p] = 0ull;
}

// ---------------- tcgen05 helpers ----------------
#if HAS_TCGEN05
__device__ __forceinline__ bool elect1() {
    uint32_t p;
    asm volatile("{\n\t.reg .pred p;\n\telect.sync _|p, 0xFFFFFFFF;\n\tselp.b32 %0,1,0,p;\n\t}" : "=r"(p));
    return p != 0;
}
__device__ __forceinline__ ull mkdesc(uint32_t addr) {
    return 0x4000404000010000ull | ((ull)(addr >> 4) & 0x3FFFull);
}
__device__ __forceinline__ void mma_ts_f16(uint32_t d, uint32_t a, ull bd, uint32_t idesc, uint32_t acc) {
    asm volatile(
        "{\n\t.reg .pred p;\n\tsetp.ne.u32 p, %5, 0;\n\t"
        "tcgen05.mma.cta_group::1.kind::f16 [%0], [%1], %2, %3, {%4,%4,%4,%4}, p;\n\t}"
        :: "r"(d), "r"(a), "l"(bd), "r"(idesc), "r"(0u), "r"(acc) : "memory");
}
__device__ __forceinline__ void tc_commit(uint32_t mbar) {
    asm volatile("tcgen05.commit.cta_group::1.mbarrier::arrive::one.shared::cluster.b64 [%0];"
                 :: "r"(mbar) : "memory");
}
__device__ __forceinline__ void mbar_init(uint32_t a, uint32_t cnt) {
    asm volatile("mbarrier.init.shared.b64 [%0], %1;" :: "r"(a), "r"(cnt) : "memory");
}
__device__ __forceinline__ void mbar_wait(uint32_t a, uint32_t ph) {
    asm volatile(
        "{\n\t.reg .pred P;\n\tLW%=:\n\t"
        "mbarrier.try_wait.parity.acquire.cta.shared::cta.b64 P, [%0], %1;\n\t"
        "@!P bra LW%=;\n\t}"
        :: "r"(a), "r"(ph) : "memory");
}
#define TC_WAIT_LD()   asm volatile("tcgen05.wait::ld.sync.aligned;" ::: "memory")
#define TC_WAIT_ST()   asm volatile("tcgen05.wait::st.sync.aligned;" ::: "memory")
#define TC_FENCE_B()   asm volatile("tcgen05.fence::before_thread_sync;" ::: "memory")
#define TC_FENCE_A()   asm volatile("tcgen05.fence::after_thread_sync;" ::: "memory")
#define FENCE_PROXY()  asm volatile("fence.proxy.async.shared::cta;" ::: "memory")

__device__ __forceinline__ void ldtm32(uint32_t* r, uint32_t a) {
    asm volatile(
        "tcgen05.ld.sync.aligned.32x32b.x32.b32 "
        "{%0,%1,%2,%3,%4,%5,%6,%7,%8,%9,%10,%11,%12,%13,%14,%15,"
        "%16,%17,%18,%19,%20,%21,%22,%23,%24,%25,%26,%27,%28,%29,%30,%31}, [%32];"
        : "=r"(r[0]), "=r"(r[1]), "=r"(r[2]), "=r"(r[3]), "=r"(r[4]), "=r"(r[5]), "=r"(r[6]), "=r"(r[7]),
          "=r"(r[8]), "=r"(r[9]), "=r"(r[10]), "=r"(r[11]), "=r"(r[12]), "=r"(r[13]), "=r"(r[14]), "=r"(r[15]),
          "=r"(r[16]), "=r"(r[17]), "=r"(r[18]), "=r"(r[19]), "=r"(r[20]), "=r"(r[21]), "=r"(r[22]), "=r"(r[23]),
          "=r"(r[24]), "=r"(r[25]), "=r"(r[26]), "=r"(r[27]), "=r"(r[28]), "=r"(r[29]), "=r"(r[30]), "=r"(r[31])
        : "r"(a));
}
__device__ __forceinline__ void sttm_x8(uint32_t a, const uint32_t* r) {
    asm volatile(
        "tcgen05.st.sync.aligned.32x32b.x8.b32 [%0], {%1,%2,%3,%4,%5,%6,%7,%8};"
        :: "r"(a), "r"(r[0]), "r"(r[1]), "r"(r[2]), "r"(r[3]),
           "r"(r[4]), "r"(r[5]), "r"(r[6]), "r"(r[7]) : "memory");
}
__device__ __forceinline__ void sttm_x16(uint32_t a, const uint32_t* r) {
    asm volatile(
        "tcgen05.st.sync.aligned.32x32b.x16.b32 [%0], "
        "{%1,%2,%3,%4,%5,%6,%7,%8,%9,%10,%11,%12,%13,%14,%15,%16};"
        :: "r"(a), "r"(r[0]), "r"(r[1]), "r"(r[2]), "r"(r[3]),
           "r"(r[4]), "r"(r[5]), "r"(r[6]), "r"(r[7]),
           "r"(r[8]), "r"(r[9]), "r"(r[10]), "r"(r[11]),
           "r"(r[12]), "r"(r[13]), "r"(r[14]), "r"(r[15]) : "memory");
}

__device__ __forceinline__ uint32_t swz_bf16(int row, int col, int nar) {
    uint32_t b = (uint32_t)((row >> 3) + (col >> 6) * nar) * 1024u
               + (uint32_t)(row & 7) * 128u + (uint32_t)(col & 63) * 2u;
    return b ^ ((b >> 3) & 0x70u);
}

__device__ __forceinline__ void pack_hilo(float v0, float v1, uint32_t& h, uint32_t& l) {
    asm("cvt.rn.bf16x2.f32 %0, %1, %2;" : "=r"(h) : "f"(v1), "f"(v0));
    float h0 = __uint_as_float(h << 16);
    float h1 = __uint_as_float(h & 0xffff0000u);
    asm("cvt.rn.bf16x2.f32 %0, %1, %2;" : "=r"(l) : "f"(v1 - h1), "f"(v0 - h0));
}
#endif  // HAS_TCGEN05

// ---------------- zero kernels (split by consumer for graph parallelism) ----------------
__global__ void k_zero_fh() {   // aggH + cntH (host-chain inputs)
    size_t i = (size_t)blockIdx.x * blockDim.x + threadIdx.x;
    size_t stride = (size_t)gridDim.x * blockDim.x;
    const float4 z = make_float4(0.f, 0.f, 0.f, 0.f);
    for (size_t k = i; k < ((size_t)N_HOST * D_IN) / 4; k += stride) ((float4*)g_aggH)[k] = z;
    for (size_t k = i; k < (size_t)N_HOST / 4; k += stride) ((float4*)g_cntH)[k] = z;
}
__global__ void k_zero_hf() {   // aggX + cntF (flow inputs)
    size_t i = (size_t)blockIdx.x * blockDim.x + threadIdx.x;
    size_t stride = (size_t)gridDim.x * blockDim.x;
    const float4 z = make_float4(0.f, 0.f, 0.f, 0.f);
    for (size_t k = i; k < ((size_t)N_FLOW * D_IN) / 4; k += stride) ((float4*)g_aggX)[k] = z;
    for (size_t k = i; k < (size_t)N_FLOW / 4; k += stride) ((float4*)g_cntF)[k] = z;
}
__global__ void k_zero_a2() {   // agg2
    size_t i = (size_t)blockIdx.x * blockDim.x + threadIdx.x;
    size_t stride = (size_t)gridDim.x * blockDim.x;
    const float4 z = make_float4(0.f, 0.f, 0.f, 0.f);
    for (size_t k = i; k < ((size_t)N_FLOW * D_H) / 4; k += stride) ((float4*)g_agg2)[k] = z;
}

// ---------------- 64-dim edge scatter ----------------
__global__ __launch_bounds__(256) void k_scatter64(
    const float* __restrict__ feat, const int* __restrict__ src,
    const int* __restrict__ dst, float* __restrict__ agg, float* __restrict__ cnt)
{
    int eloc = threadIdx.x >> 4;
    int lane = threadIdx.x & 15;
    int e = blockIdx.x * 16 + eloc;
    if (e >= NE) return;
    int s = __ldg(src + e);
    int d = __ldg(dst + e);
    float4 v = *(const float4*)(feat + (size_t)s * 64 + lane * 4);
    float* p = agg + (size_t)d * 64 + lane * 4;
    asm volatile("red.global.add.v4.f32 [%0], {%1,%2,%3,%4};"
                 :: "l"(p), "f"(v.x), "f"(v.y), "f"(v.z), "f"(v.w) : "memory");
    if (lane == 0) atomicAdd(cnt + d, 1.0f);
}

// ---------------- 128-dim scatter (th1 -> agg2) ----------------
__global__ __launch_bounds__(256) void k_scatter128(
    const float* __restrict__ feat, const int* __restrict__ src,
    const int* __restrict__ dst, float* __restrict__ agg, int E)
{
    int eloc = threadIdx.x >> 5;
    int lane = threadIdx.x & 31;
    int e = blockIdx.x * 8 + eloc;
    if (e >= E) return;
    int s = __ldg(src + e);
    int d = __ldg(dst + e);
    float4 v = *(const float4*)(feat + (size_t)s * 128 + lane * 4);
    float* p = agg + (size_t)d * 128 + lane * 4;
    asm volatile("red.global.add.v4.f32 [%0], {%1,%2,%3,%4};"
                 :: "l"(p), "f"(v.x), "f"(v.y), "f"(v.z), "f"(v.w) : "memory");
}

// ---------------- fused host chain (FFMA2, stacked K=128) ----------------
struct HostSmem {
    float Ws0[128 * 128];
    float Ws1[128 * 128];
    float Buf[128 * 132];
};

__global__ __launch_bounds__(256, 1) void k_host(
    const float* __restrict__ aggH, const float* __restrict__ cntH,
    const float* __restrict__ xh,
    const float* __restrict__ W0l, const float* __restrict__ W0r,
    const float* __restrict__ b0,
    const float* __restrict__ W1l,
    float* __restrict__ th1)
{
    HostSmem* S = reinterpret_cast<HostSmem*>(smem_raw);
    const int tid = threadIdx.x;
    for (int i = tid; i < 128 * 128; i += 256) {
        int k = i >> 7, n = i & 127;
        S->Ws0[i] = (k < 64) ? W0l[k * 128 + n] : W0r[(k - 64) * 128 + n];
    }
    for (int f = tid; f < 128 * 128 / 4; f += 256) ((float4*)S->Ws1)[f] = ((const float4*)W1l)[f];

    const int tr8 = (tid >> 4) * 8;
    const int tc8 = (tid & 15) * 8;
    float b0r[8];
#pragma unroll
    for (int j = 0; j < 8; j++) b0r[j] = b0[tc8 + j];

    const int NT = (N_HOST + 127) / 128;
    for (int tile = blockIdx.x; tile < NT; tile += gridDim.x) {
        const int row0 = tile * 128;
        __syncthreads();
        for (int f = tid; f < 4096; f += 256) {
            int r = f >> 5, cc = (f & 31) * 4;
            int gr = row0 + r;
            if (gr >= N_HOST) continue;
            float4 v;
            if (cc < 64) {
                float inv = 1.f / fmaxf(__ldg(cntH + gr), 1.f);
                v = *(const float4*)(aggH + (size_t)gr * 64 + cc);
                v.x *= inv; v.y *= inv; v.z *= inv; v.w *= inv;
            } else {
                v = *(const float4*)(xh + (size_t)gr * 64 + (cc - 64));
            }
            *(float4*)(&S->Buf[r * 132 + cc]) = v;
        }
        __syncthreads();

        ull acc[8][4];
        zero_acc(acc);
        mma_tile<128, 132>(S->Buf, S->Ws0, tr8, tc8, acc);
        __syncthreads();
#pragma unroll
        for (int i = 0; i < 8; i++) {
#pragma unroll
            for (int p = 0; p < 4; p++) {
                float2 v = *reinterpret_cast<float2*>(&acc[i][p]);
                S->Buf[(tr8 + i) * 132 + tc8 + 2 * p]     = lrelu(v.x + b0r[2 * p]);
                S->Buf[(tr8 + i) * 132 + tc8 + 2 * p + 1] = lrelu(v.y + b0r[2 * p + 1]);
            }
        }
        __syncthreads();

        zero_acc(acc);
        mma_tile<128, 132>(S->Buf, S->Ws1, tr8, tc8, acc);
#pragma unroll
        for (int i = 0; i < 8; i++) {
            int gr = row0 + tr8 + i;
            if (gr >= N_HOST) continue;
            float2 v0 = *reinterpret_cast<float2*>(&acc[i][0]);
            float2 v1 = *reinterpret_cast<float2*>(&acc[i][1]);
            float2 v2 = *reinterpret_cast<float2*>(&acc[i][2]);
            float2 v3 = *reinterpret_cast<float2*>(&acc[i][3]);
            *(float4*)(th1 + (size_t)gr * 128 + tc8)     = make_float4(v0.x, v0.y, v1.x, v1.y);
            *(float4*)(th1 + (size_t)gr * 128 + tc8 + 4) = make_float4(v2.x, v2.y, v3.x, v3.y);
        }
    }
}

// ================= flow chain (paired-tile tcgen05 pipeline) =================
#define O_W01H 0
#define O_W01L 32768
#define O_W1H  65536
#define O_W1L  98304
#define O_WOH  131072
#define O_WOL  139264
#define O_B0   147456
#define O_B1   147968
#define O_BO   148480
#define O_MB   148608          // 6 mbarriers (48 B)
#define O_TP   148656
// TMEM columns: A slot0 [0,128), A slot1 [128,256), D slot0 [256,384), D slot1 [384,512)
#define TM_SA0 0
#define TM_SA1 128
#define TM_SD0 256
#define TM_SD1 384

#define FLOW_SMEM_REQ 231936   // covers FFMA2 fallback too

__global__ __launch_bounds__(256, 1)
void k_flow_tc(const float* __restrict__ xf,
               const float* __restrict__ aggX, const float* __restrict__ agg2,
               const float* __restrict__ cnt,
               const float* __restrict__ W0r, const float* __restrict__ W0l,
               const float* __restrict__ b0,
               const float* __restrict__ W1r, const float* __restrict__ b1,
               const float* __restrict__ Wo,  const float* __restrict__ bo,
               float* __restrict__ out)
{
#if HAS_TCGEN05
    const int tid = threadIdx.x;
    const int wid = tid >> 5;
    const int lane = tid & 31;

    uint32_t raw = smem_u32(smem_raw);
    uint32_t base = (raw + 1023u) & ~1023u;
    char* sp = smem_raw + (base - raw);

    char* pW01H = sp + O_W01H; char* pW01L = sp + O_W01L;
    char* pW1H  = sp + O_W1H;  char* pW1L  = sp + O_W1L;
    char* pWOH  = sp + O_WOH;  char* pWOL  = sp + O_WOL;
    float* b0s = (float*)(sp + O_B0);
    float* b1s = (float*)(sp + O_B1);
    float* bos = (float*)(sp + O_BO);
    const uint32_t MB = base + O_MB;

    // ---- one-time weight prep ----
    for (int i = tid; i < 128 * 128; i += 256) {     // stacked [W0r; W0l] -> B(n,k)
        int k = i >> 7, n = i & 127;
        float v = (k < 64) ? W0r[k * 128 + n] : W0l[(k - 64) * 128 + n];
        __nv_bfloat16 h = __float2bfloat16(v);
        __nv_bfloat16 l = __float2bfloat16(v - __bfloat162float(h));
        uint32_t o = swz_bf16(n, k, 16);
        *(__nv_bfloat16*)(pW01H + o) = h;
        *(__nv_bfloat16*)(pW01L + o) = l;
    }
    for (int i = tid; i < 128 * 128; i += 256) {     // W1r -> B(n,k)
        int k = i >> 7, n = i & 127;
        float v = W1r[i];
        __nv_bfloat16 h = __float2bfloat16(v);
        __nv_bfloat16 l = __float2bfloat16(v - __bfloat162float(h));
        uint32_t o = swz_bf16(n, k, 16);
        *(__nv_bfloat16*)(pW1H + o) = h;
        *(__nv_bfloat16*)(pW1L + o) = l;
    }
    for (int i = tid; i < 128 * 32; i += 256) {      // Wo -> B(n,k)
        int k = i >> 5, n = i & 31;
        float v = Wo[i];
        __nv_bfloat16 h = __float2bfloat16(v);
        __nv_bfloat16 l = __float2bfloat16(v - __bfloat162float(h));
        uint32_t o = swz_bf16(n, k, 4);
        *(__nv_bfloat16*)(pWOH + o) = h;
        *(__nv_bfloat16*)(pWOL + o) = l;
    }
    for (int i = tid; i < 128; i += 256) { b0s[i] = b0[i]; b1s[i] = b1[i]; }
    if (tid < 32) bos[tid] = bo[tid];
    if (tid == 0) {
#pragma unroll
        for (int m = 0; m < 6; m++) mbar_init(MB + 8 * m, 1);
    }
    if (wid == 0) {
        asm volatile("tcgen05.alloc.cta_group::1.sync.aligned.shared::cta.b32 [%0], %1;"
                     :: "r"(base + O_TP), "r"(512) : "memory");
    }
    FENCE_PROXY();
    __syncthreads();
    uint32_t tmem;
    asm volatile("ld.shared.b32 %0, [%1];" : "=r"(tmem) : "r"(base + O_TP));

    const ull d0H = mkdesc(base + O_W01H), d0L = mkdesc(base + O_W01L);
    const ull d1H = mkdesc(base + O_W1H),  d1L = mkdesc(base + O_W1L);
    const ull dOH = mkdesc(base + O_WOH),  dOL = mkdesc(base + O_WOL);
    const uint32_t idesc128 = 0x8200490u;
    const uint32_t idesc32  = 0x8080490u;

    const int sub = wid & 3, half = wid >> 2;
    const int r = sub * 32 + lane;
    const uint32_t tm_row = (uint32_t)sub << 21;
    const int c0a = half * 32;
    const int c0b = 64 + half * 32;

    const uint32_t SA0 = tmem + TM_SA0, SA1 = tmem + TM_SA1;
    const uint32_t SD0 = tmem + TM_SD0, SD1 = tmem + TM_SD1;

    const int NT = (N_FLOW + 127) >> 7;       // 1563
    const int NP = (NT + 1) >> 1;             // 782 pairs

    const int BOW[8] = {0, 2, 4, 6, 1024, 1026, 1028, 1030};
    const int BOO[8] = {0, 2, 4, 6, 256, 258, 260, 262};

    // warp-collective A loader: [x | aggX*inv] -> TMEM slot; returns inv of this thread's row
    auto load_A = [&](int row0n, uint32_t slot) -> float {
        int gn = row0n + r;
        int gs = gn < N_FLOW ? gn : N_FLOW - 1;
        float inv = 1.f / fmaxf(__ldg(cnt + gs), 1.f);
        const float* src = half ? (aggX + (size_t)gs * 64) : (xf + (size_t)gs * 64);
        float sc = half ? inv : 1.f;
        uint32_t A0 = slot + (uint32_t)(half * 32) + tm_row;
#pragma unroll
        for (int q = 0; q < 4; q++) {
            const float4* p4 = (const float4*)(src + q * 16);
            float4 f0 = p4[0], f1 = p4[1], f2 = p4[2], f3 = p4[3];
            float e[16] = {f0.x, f0.y, f0.z, f0.w, f1.x, f1.y, f1.z, f1.w,
                           f2.x, f2.y, f2.z, f2.w, f3.x, f3.y, f3.z, f3.w};
            uint32_t hi[8], lo[8];
#pragma unroll
            for (int i = 0; i < 8; i++) pack_hilo(e[2 * i] * sc, e[2 * i + 1] * sc, hi[i], lo[i]);
            sttm_x8(A0 + q * 8, hi);
            sttm_x8(A0 + 64 + q * 8, lo);
        }
        TC_WAIT_ST();
        return inv;
    };

    auto mma_phase = [&](uint32_t a0, uint32_t dD, ull bh, ull bl, const int* BO, uint32_t idesc) {
#pragma unroll
        for (int s = 0; s < 8; s++) mma_ts_f16(dD, a0 + s * 8, bh + BO[s], idesc, s > 0);
#pragma unroll
        for (int s = 0; s < 8; s++) mma_ts_f16(dD, a0 + s * 8, bl + BO[s], idesc, 1);
#pragma unroll
        for (int s = 0; s < 8; s++) mma_ts_f16(dD, a0 + 64 + s * 8, bh + BO[s], idesc, 1);
    };

    // epilogue 1: H = lrelu(D + b0) -> A slot
    auto epi1 = [&](uint32_t dSlot, uint32_t aSlot) {
        uint32_t dr[32], hi[16], lo[16];
        ldtm32(dr, dSlot + c0a + tm_row);
        TC_WAIT_LD();
#pragma unroll
        for (int j = 0; j < 32; j += 2) {
            float v0 = lrelu(__uint_as_float(dr[j])     + b0s[c0a + j]);
            float v1 = lrelu(__uint_as_float(dr[j + 1]) + b0s[c0a + j + 1]);
            pack_hilo(v0, v1, hi[j >> 1], lo[j >> 1]);
        }
        sttm_x16(aSlot + (c0a >> 1) + tm_row, hi);
        sttm_x16(aSlot + 64 + (c0a >> 1) + tm_row, lo);
        ldtm32(dr, dSlot + c0b + tm_row);
        TC_WAIT_LD();
#pragma unroll
        for (int j = 0; j < 32; j += 2) {
            float v0 = lrelu(__uint_as_float(dr[j])     + b0s[c0b + j]);
            float v1 = lrelu(__uint_as_float(dr[j + 1]) + b0s[c0b + j + 1]);
            pack_hilo(v0, v1, hi[j >> 1], lo[j >> 1]);
        }
        sttm_x16(aSlot + (c0b >> 1) + tm_row, hi);
        sttm_x16(aSlot + 64 + (c0b >> 1) + tm_row, lo);
        TC_WAIT_ST();
    };

    auto prefetch2 = [&](int ge, float4* q0, float4* q1) {
        int gs = ge < N_FLOW ? ge : N_FLOW - 1;
        const float4* ap = (const float4*)(agg2 + (size_t)gs * 128);
#pragma unroll
        for (int i = 0; i < 8; i++) q0[i] = ap[(c0a >> 2) + i];
#pragma unroll
        for (int i = 0; i < 8; i++) q1[i] = ap[(c0b >> 2) + i];
    };

    // epilogue 2: g = lrelu(D + agg2*inv + b1) -> A slot
    auto epi2 = [&](uint32_t dSlot, uint32_t aSlot, const float4* q0, const float4* q1, float inv) {
        uint32_t dr[32], hi[16], lo[16];
        ldtm32(dr, dSlot + c0a + tm_row);
        TC_WAIT_LD();
#pragma unroll
        for (int j = 0; j < 32; j += 4) {
            float4 av = q0[j >> 2];
            float v0 = lrelu(__uint_as_float(dr[j])     + av.x * inv + b1s[c0a + j]);
            float v1 = lrelu(__uint_as_float(dr[j + 1]) + av.y * inv + b1s[c0a + j + 1]);
            float v2 = lrelu(__uint_as_float(dr[j + 2]) + av.z * inv + b1s[c0a + j + 2]);
            float v3 = lrelu(__uint_as_float(dr[j + 3]) + av.w * inv + b1s[c0a + j + 3]);
            pack_hilo(v0, v1, hi[j >> 1], lo[j >> 1]);
            pack_hilo(v2, v3, hi[(j >> 1) + 1], lo[(j >> 1) + 1]);
        }
        sttm_x16(aSlot + (c0a >> 1) + tm_row, hi);
        sttm_x16(aSlot + 64 + (c0a >> 1) + tm_row, lo);
        ldtm32(dr, dSlot + c0b + tm_row);
        TC_WAIT_LD();
#pragma unroll
        for (int j = 0; j < 32; j += 4) {
            float4 av = q1[j >> 2];
            float v0 = lrelu(__uint_as_float(dr[j])     + av.x * inv + b1s[c0b + j]);
            float v1 = lrelu(__uint_as_float(dr[j + 1]) + av.y * inv + b1s[c0b + j + 1]);
            float v2 = lrelu(__uint_as_float(dr[j + 2]) + av.z * inv + b1s[c0b + j + 2]);
            float v3 = lrelu(__uint_as_float(dr[j + 3]) + av.w * inv + b1s[c0b + j + 3]);
            pack_hilo(v0, v1, hi[j >> 1], lo[j >> 1]);
            pack_hilo(v2, v3, hi[(j >> 1) + 1], lo[(j >> 1) + 1]);
        }
        sttm_x16(aSlot + (c0b >> 1) + tm_row, hi);
        sttm_x16(aSlot + 64 + (c0b >> 1) + tm_row, lo);
        TC_WAIT_ST();
    };

    // epilogue 3: out = D + bout
    auto epi3 = [&](uint32_t dSlot, int ge) {
        if (wid >= 4) return;
        uint32_t dr[32];
        ldtm32(dr, dSlot + tm_row);
        TC_WAIT_LD();
        if (ge < N_FLOW) {
            float* op = out + (size_t)ge * 32;
#pragma unroll
            for (int c = 0; c < 32; c += 4) {
                *(float4*)(op + c) = make_float4(
                    __uint_as_float(dr[c])     + bos[c],
                    __uint_as_float(dr[c + 1]) + bos[c + 1],
                    __uint_as_float(dr[c + 2]) + bos[c + 2],
                    __uint_as_float(dr[c + 3]) + bos[c + 3]);
            }
        }
    };

    int it = 0;
    for (int p = blockIdx.x; p < NP; p += gridDim.x, ++it) {
        const int tileA = 2 * p, tileB = tileA + 1;
        const bool vB = tileB < NT;
        const int row0A = tileA << 7, row0B = tileB << 7;
        const int geA = row0A + r, geB = row0B + r;
        const int par = it & 1;
        __syncthreads();                     // prior iteration fully retired

        // ---- load both A tiles ----
        float invA = load_A(row0A, SA0);
        float invB = 1.f;
        if (vB) invB = load_A(row0B, SA1);
        TC_FENCE_B();
        __syncthreads();

        // ---- phase 1 MMAs (A then B) ----
        if (wid == 0) {
            TC_FENCE_A();
            if (elect1()) {
                mma_phase(SA0, SD0, d0H, d0L, BOW, idesc128); tc_commit(MB + 0);
                if (vB) { mma_phase(SA1, SD1, d0H, d0L, BOW, idesc128); tc_commit(MB + 8); }
            }
        }

        // ---- epi1(A) -> MMA2(A) ----
        mbar_wait(MB + 0, par); TC_FENCE_A();
        epi1(SD0, SA0);
        TC_FENCE_B(); __syncthreads();
        if (wid == 0) {
            TC_FENCE_A();
            if (elect1()) { mma_phase(SA0, SD0, d1H, d1L, BOW, idesc128); tc_commit(MB + 16); }
        }
        float4 qa0[8], qa1[8];
        prefetch2(geA, qa0, qa1);            // overlaps MMA1(B)/MMA2(A)

        // ---- epi1(B) -> MMA2(B) ----
        if (vB) {
            mbar_wait(MB + 8, par); TC_FENCE_A();
            epi1(SD1, SA1);
            TC_FENCE_B(); __syncthreads();
            if (wid == 0) {
                TC_FENCE_A();
                if (elect1()) { mma_phase(SA1, SD1, d1H, d1L, BOW, idesc128); tc_commit(MB + 24); }
            }
        }

        // ---- epi2(A) -> MMA3(A) ----
        mbar_wait(MB + 16, par); TC_FENCE_A();
        epi2(SD0, SA0, qa0, qa1, invA);
        TC_FENCE_B(); __syncthreads();
        if (wid == 0) {
            TC_FENCE_A();
            if (elect1()) { mma_phase(SA0, SD0, dOH, dOL, BOO, idesc32); tc_commit(MB + 32); }
        }

        // ---- epi2(B) -> MMA3(B) ----
        if (vB) {
            float4 qb0[8], qb1[8];
            prefetch2(geB, qb0, qb1);        // overlaps MMA2(B) tail / MMA3(A)
            mbar_wait(MB + 24, par); TC_FENCE_A();
            epi2(SD1, SA1, qb0, qb1, invB);
            TC_FENCE_B(); __syncthreads();
            if (wid == 0) {
                TC_FENCE_A();
                if (elect1()) { mma_phase(SA1, SD1, dOH, dOL, BOO, idesc32); tc_commit(MB + 40); }
            }
        }

        // ---- epi3 ----
        mbar_wait(MB + 32, par); TC_FENCE_A();
        epi3(SD0, geA);
        if (vB) {
            mbar_wait(MB + 40, par); TC_FENCE_A();
            epi3(SD1, geB);
        }
        TC_FENCE_B();
    }

    __syncthreads();
    if (wid == 0) {
        asm volatile("tcgen05.relinquish_alloc_permit.cta_group::1.sync.aligned;");
        asm volatile("tcgen05.dealloc.cta_group::1.sync.aligned.b32 %0, %1;" :: "r"(tmem), "r"(512));
    }
#else
    // ==================== FFMA2 fallback path ====================
    float* Ws0a = (float*)smem_raw;
    float* Ws0b = Ws0a + 64 * 128;
    float* Ws1  = Ws0b + 64 * 128;
    float* Asf  = Ws1 + 128 * 128;
    float* H    = Asf + 128 * 68;

    const int tid = threadIdx.x;
    for (int f = tid; f < 64 * 128 / 4; f += 256) {
        ((float4*)Ws0a)[f] = ((const float4*)W0r)[f];
        ((float4*)Ws0b)[f] = ((const float4*)W0l)[f];
    }
    for (int f = tid; f < 128 * 128 / 4; f += 256) ((float4*)Ws1)[f] = ((const float4*)W1r)[f];

    const int tr8 = (tid >> 4) * 8;
    const int tc8 = (tid & 15) * 8;
    float b0r[8], b1r[8];
#pragma unroll
    for (int j = 0; j < 8; j++) { b0r[j] = b0[tc8 + j]; b1r[j] = b1[tc8 + j]; }
    const int r4 = (tid >> 3) * 4;
    const int c4 = (tid & 7) * 4;
    float bor[4];
#pragma unroll
    for (int j = 0; j < 4; j++) bor[j] = bo[c4 + j];

    const int NT = (N_FLOW + 127) / 128;
    for (int tile = blockIdx.x; tile < NT; tile += gridDim.x) {
        const int row0 = tile * 128;
        __syncthreads();
        for (int f = tid; f < 2048; f += 256) {
            int r = f >> 4, cc = (f & 15) * 4;
            int gr = row0 + r;
            if (gr < N_FLOW)
                *(float4*)(Asf + r * 68 + cc) = *(const float4*)(xf + (size_t)gr * 64 + cc);
        }
        __syncthreads();

        ull acc[8][4];
        zero_acc(acc);
        mma_tile<64, 68>(Asf, Ws0a, tr8, tc8, acc);
        __syncthreads();
        for (int f = tid; f < 2048; f += 256) {
            int r = f >> 4, cc = (f & 15) * 4;
            int gr = row0 + r;
            if (gr < N_FLOW) {
                float inv = 1.f / fmaxf(__ldg(cnt + gr), 1.f);
                float4 v = *(const float4*)(aggX + (size_t)gr * 64 + cc);
                v.x *= inv; v.y *= inv; v.z *= inv; v.w *= inv;
                *(float4*)(Asf + r * 68 + cc) = v;
            }
        }
        __syncthreads();
        mma_tile<64, 68>(Asf, Ws0b, tr8, tc8, acc);

#pragma unroll
        for (int i = 0; i < 8; i++) {
            int gr = row0 + tr8 + i;
            if (gr >= N_FLOW) continue;
#pragma unroll
            for (int p = 0; p < 4; p++) {
                float2 v = *reinterpret_cast<float2*>(&acc[i][p]);
                H[(tr8 + i) * 129 + tc8 + 2 * p]     = lrelu(v.x + b0r[2 * p]);
                H[(tr8 + i) * 129 + tc8 + 2 * p + 1] = lrelu(v.y + b0r[2 * p + 1]);
            }
        }
        __syncthreads();

        zero_acc(acc);
        mma_tile<128, 129>(H, Ws1, tr8, tc8, acc);
        __syncthreads();
#pragma unroll
        for (int i = 0; i < 8; i++) {
            int gr = row0 + tr8 + i;
            if (gr >= N_FLOW) continue;
            float inv = 1.f / fmaxf(__ldg(cnt + gr), 1.f);
            float4 p0 = *(const float4*)(agg2 + (size_t)gr * 128 + tc8);
            float4 p1 = *(const float4*)(agg2 + (size_t)gr * 128 + tc8 + 4);
            float pv[8] = {p0.x, p0.y, p0.z, p0.w, p1.x, p1.y, p1.z, p1.w};
#pragma unroll
            for (int p = 0; p < 4; p++) {
                float2 v = *reinterpret_cast<float2*>(&acc[i][p]);
                H[(tr8 + i) * 129 + tc8 + 2 * p]     = lrelu(v.x + pv[2 * p] * inv + b1r[2 * p]);
                H[(tr8 + i) * 129 + tc8 + 2 * p + 1] = lrelu(v.y + pv[2 * p + 1] * inv + b1r[2 * p + 1]);
            }
        }
        __syncthreads();

        ull acc3[4][2];
#pragma unroll
        for (int i = 0; i < 4; i++) { acc3[i][0] = 0ull; acc3[i][1] = 0ull; }
#pragma unroll 4
        for (int kk = 0; kk < 128; kk++) {
            float4 wv = __ldg((const float4*)(Wo + kk * 32 + c4));
            ull wx, wy;
            asm("mov.b64 %0, {%1, %2};" : "=l"(wx) : "f"(wv.x), "f"(wv.y));
            asm("mov.b64 %0, {%1, %2};" : "=l"(wy) : "f"(wv.z), "f"(wv.w));
#pragma unroll
            for (int i = 0; i < 4; i++) {
                ull ad = dup2(H[(r4 + i) * 129 + kk]);
                ffma2(acc3[i][0], ad, wx);
                ffma2(acc3[i][1], ad, wy);
            }
        }
#pragma unroll
        for (int i = 0; i < 4; i++) {
            int gr = row0 + r4 + i;
            if (gr >= N_FLOW) continue;
            float2 v0 = *reinterpret_cast<float2*>(&acc3[i][0]);
            float2 v1 = *reinterpret_cast<float2*>(&acc3[i][1]);
            *(float4*)(out + (size_t)gr * 32 + c4) =
                make_float4(v0.x + bor[0], v0.y + bor[1], v1.x + bor[2], v1.y + bor[3]);
        }
    }
#endif
}

// ---------------- host launcher (multi-stream graph fork/join) ----------------
extern "C" void kernel_launch(void* const* d_in, const int* in_sizes, int n_in,
                              void* d_out, int out_size)
{
    const float* x_host  = (const float*)d_in[0];
    const float* x_flow  = (const float*)d_in[1];
    const int*   src_hf  = (const int*)d_in[2];
    const int*   dst_hf  = (const int*)d_in[3];
    const int*   src_fh  = (const int*)d_in[4];
    const int*   dst_fh  = (const int*)d_in[5];
    const float* W0_hf_l = (const float*)d_in[6];
    const float* W0_hf_r = (const float*)d_in[7];
    const float* b0_hf   = (const float*)d_in[8];
    const float* W0_fh_l = (const float*)d_in[9];
    const float* W0_fh_r = (const float*)d_in[10];
    const float* b0_fh   = (const float*)d_in[11];
    const float* W1_hf_l = (const float*)d_in[12];
    const float* W1_hf_r = (const float*)d_in[13];
    const float* b1_hf   = (const float*)d_in[14];
    // d_in[15..17] unused (g_host discarded)
    const float* W_out   = (const float*)d_in[18];
    const float* b_out   = (const float*)d_in[19];
    float* out = (float*)d_out;

    float *aggX, *cntF, *aggH, *cntH, *th1, *agg2;
    cudaGetSymbolAddress((void**)&aggX, g_aggX);
    cudaGetSymbolAddress((void**)&cntF, g_cntF);
    cudaGetSymbolAddress((void**)&aggH, g_aggH);
    cudaGetSymbolAddress((void**)&cntH, g_cntH);
    cudaGetSymbolAddress((void**)&th1,  g_th1);
    cudaGetSymbolAddress((void**)&agg2, g_agg2);

    cudaFuncSetAttribute(k_host, cudaFuncAttributeMaxDynamicSharedMemorySize, (int)sizeof(HostSmem));
    cudaFuncSetAttribute(k_flow_tc, cudaFuncAttributeMaxDynamicSharedMemorySize, FLOW_SMEM_REQ);

    static cudaStream_t s1 = nullptr, s2 = nullptr;
    static cudaEvent_t evFork = nullptr, evFh = nullptr, evHf = nullptr, evA2 = nullptr;
    if (s1 == nullptr) {
        cudaStreamCreateWithFlags(&s1, cudaStreamNonBlocking);
        cudaStreamCreateWithFlags(&s2, cudaStreamNonBlocking);
        cudaEventCreateWithFlags(&evFork, cudaEventDisableTiming);
        cudaEventCreateWithFlags(&evFh, cudaEventDisableTiming);
        cudaEventCreateWithFlags(&evHf, cudaEventDisableTiming);
        cudaEventCreateWithFlags(&evA2, cudaEventDisableTiming);
    }

    // Fork side streams off the origin stream.
    cudaEventRecord(evFork, 0);
    cudaStreamWaitEvent(s1, evFork, 0);
    cudaStreamWaitEvent(s2, evFork, 0);

    // Origin: zero fh-aggregates -> fh-scatter -> host chain
    k_zero_fh<<<256, 256>>>();
    k_scatter64<<<(NE + 15) / 16, 256>>>(x_flow, src_fh, dst_fh, aggH, cntH);
    cudaEventRecord(evFh, 0);
    k_host<<<157, 256, sizeof(HostSmem)>>>(aggH, cntH, x_host,
                                           W0_fh_l, W0_fh_r, b0_fh, W1_hf_l, th1);

    // s1: zero hf-aggregates, then hf-scatter AFTER fh-scatter finishes (runs under k_host)
    k_zero_hf<<<1024, 256, 0, s1>>>();
    cudaStreamWaitEvent(s1, evFh, 0);
    k_scatter64<<<(NE + 15) / 16, 256, 0, s1>>>(x_host, src_hf, dst_hf, aggX, cntF);
    cudaEventRecord(evHf, s1);

    // s2: zero agg2 (off the critical path)
    k_zero_a2<<<2048, 256, 0, s2>>>();
    cudaEventRecord(evA2, s2);

    // Origin: join agg2-zero, 128-dim scatter, join hf-scatter, flow chain
    cudaStreamWaitEvent(0, evA2, 0);
    k_scatter128<<<(NE + 7) / 8, 256>>>(th1, src_hf, dst_hf, agg2, NE);
    cudaStreamWaitEvent(0, evHf, 0);
    k_flow_tc<<<148, 256, FLOW_SMEM_REQ>>>(x_flow, aggX, agg2, cntF,
                                           W0_hf_r, W0_hf_l, b0_hf,
                                           W1_hf_r, b1_hf,
                                           W_out, b_out, out);
}